// round 13
// baseline (speedup 1.0000x reference)
#include <cuda_runtime.h>
#include <cuda_bf16.h>
#include <cstddef>
#include <cstdint>

#define NMAX 100000
#define EMAX 1600000
#define CH 128

typedef unsigned long long ull;

// ------------------- device scratch (no allocations allowed) -------------------
__device__ __align__(16) float g_h   [NMAX * CH];
__device__ __align__(16) float g_xw  [NMAX * CH];   // GCN: y = xw*dinv ; attn: v
__device__ __align__(16) float g_lin [NMAX * CH];   // also num
__device__ __align__(16) float g_xloc[NMAX * CH];
__device__ __align__(16) float g_xg  [NMAX * CH];
__device__ __align__(16) float g_k   [NMAX * CH];
// split-bf16 images of x for next layer's GEMM A (pad rows for last-tile OOB)
__device__ __align__(16) __nv_bfloat16 g_xsh[(NMAX + 128) * CH];
__device__ __align__(16) __nv_bfloat16 g_xsl[(NMAX + 128) * CH];
__device__ __align__(16) float g_dinv[NMAX];
__device__ int   g_deg [NMAX];
__device__ int   g_rowp[NMAX + 1];
__device__ int   g_fill[NMAX];
__device__ int   g_col [EMAX];
__device__ int   g_bsum[64];
__device__ int   g_is64;
// kv [128][128] followed by ksum[128]
__device__ __align__(16) float g_kvs [CH * CH + CH];
// pre-split bf16 weights, row-major [n=128][k=128] per slot (slot 30 = kv)
__device__ __align__(16) __nv_bfloat16 g_Bhi[31 * 16384];
__device__ __align__(16) __nv_bfloat16 g_Blo[31 * 16384];

// ------------------- f32x2 helpers (kv kernel) -------------------
__device__ __forceinline__ ull fma2(ull a, ull b, ull c) {
    ull d; asm("fma.rn.f32x2 %0, %1, %2, %3;" : "=l"(d) : "l"(a), "l"(b), "l"(c));
    return d;
}
__device__ __forceinline__ ull pk2(float v) {
    ull r; asm("mov.b64 %0, {%1, %1};" : "=l"(r) : "f"(v)); return r;
}
__device__ __forceinline__ void upk(ull v, float& lo, float& hi) {
    asm("mov.b64 {%0, %1}, %2;" : "=f"(lo), "=f"(hi) : "l"(v));
}
__device__ __forceinline__ float wsumf(float v) {
#pragma unroll
    for (int o = 16; o; o >>= 1) v += __shfl_xor_sync(0xffffffffu, v, o);
    return v;
}

// ------------------- mma / cp.async helpers -------------------
__device__ __forceinline__ uint32_t smem_u32(const void* p) {
    uint32_t a;
    asm("{ .reg .u64 t; cvta.to.shared.u64 t, %1; cvt.u32.u64 %0, t; }" : "=r"(a) : "l"(p));
    return a;
}
__device__ __forceinline__ void ldmat4(uint32_t& r0, uint32_t& r1, uint32_t& r2, uint32_t& r3,
                                       uint32_t addr) {
    asm volatile("ldmatrix.sync.aligned.m8n8.x4.shared.b16 {%0,%1,%2,%3}, [%4];"
                 : "=r"(r0), "=r"(r1), "=r"(r2), "=r"(r3) : "r"(addr));
}
__device__ __forceinline__ void mma16816(float* d, const uint32_t* a, const uint32_t* b) {
    asm volatile(
        "mma.sync.aligned.m16n8k16.row.col.f32.bf16.bf16.f32 "
        "{%0,%1,%2,%3}, {%4,%5,%6,%7}, {%8,%9}, {%0,%1,%2,%3};"
        : "+f"(d[0]), "+f"(d[1]), "+f"(d[2]), "+f"(d[3])
        : "r"(a[0]), "r"(a[1]), "r"(a[2]), "r"(a[3]), "r"(b[0]), "r"(b[1]));
}
__device__ __forceinline__ void cpa16(uint32_t dst, const void* src) {
    asm volatile("cp.async.cg.shared.global [%0], [%1], 16;" :: "r"(dst), "l"(src));
}
#define CPA_COMMIT() asm volatile("cp.async.commit_group;" ::: "memory")
#define CPA_WAIT0()  asm volatile("cp.async.wait_group 0;" ::: "memory")

__device__ __forceinline__ void splitpack(float a, float b, uint32_t& hw, uint32_t& lw) {
    __nv_bfloat16 ha = __float2bfloat16(a), hb = __float2bfloat16(b);
    float ra = a - __bfloat162float(ha), rb = b - __bfloat162float(hb);
    __nv_bfloat16 la = __float2bfloat16(ra), lb = __float2bfloat16(rb);
    __nv_bfloat162 hv(ha, hb), lv(la, lb);
    hw = *(uint32_t*)&hv; lw = *(uint32_t*)&lv;
}

// ------------------- weight prep -------------------
__global__ void prep_all(const float* __restrict__ Wh, const float* __restrict__ Wg,
                         const float* __restrict__ Wl, const float* __restrict__ gWh,
                         const float* __restrict__ gWk, const float* __restrict__ gWv,
                         const float* __restrict__ gWo, const float* __restrict__ Wp,
                         __nv_bfloat16* __restrict__ dhi, __nv_bfloat16* __restrict__ dlo)
{
    int idx = blockIdx.x * blockDim.x + threadIdx.x;
    if (idx >= 30 * 16384) return;
    int s = idx >> 14;
    const float* src; int m; int oc = 128;
    if      (s < 7)  { src = Wh;  m = s; }
    else if (s < 14) { src = Wg;  m = s - 7; }
    else if (s < 21) { src = Wl;  m = s - 14; }
    else if (s < 23) { src = gWh; m = s - 21; }
    else if (s < 25) { src = gWk; m = s - 23; }
    else if (s < 27) { src = gWv; m = s - 25; }
    else if (s < 29) { src = gWo; m = s - 27; }
    else             { src = Wp;  m = 0; oc = 40; }
    int rem = idx & 16383, o = rem >> 7, k = rem & 127;
    float v = (o < oc) ? src[(size_t)m * oc * 128 + (size_t)o * 128 + k] : 0.f;
    __nv_bfloat16 hi = __float2bfloat16(v);
    dhi[idx] = hi;
    dlo[idx] = __float2bfloat16(v - __bfloat162float(hi));
}

__global__ void prep_kv(__nv_bfloat16* __restrict__ dhi, __nv_bfloat16* __restrict__ dlo)
{
    int idx = blockIdx.x * blockDim.x + threadIdx.x;
    if (idx >= 16384) return;
    int o = idx >> 7, k = idx & 127;
    float v = g_kvs[k * 128 + o];
    __nv_bfloat16 hi = __float2bfloat16(v);
    dhi[(size_t)30 * 16384 + idx] = hi;
    dlo[(size_t)30 * 16384 + idx] = __float2bfloat16(v - __bfloat162float(hi));
}

// ------------------- tensor-core GEMM: up to 3 products sharing A -------------------
#define ACT_NONE 0
#define ACT_RELU 1
#define ACT_SIGM 2

#define AM_PLAIN 0
#define AM_LN    1
#define AM_ATTN  2
#define AM_BF16  3

struct TCParams {
    const float* A; int nrows; int nout; int amode;
    const __nv_bfloat16* Ahi; const __nv_bfloat16* Alo;   // AM_BF16
    const float* lng; const float* lnb;          // LN / ATTN params
    const float* q; const float* hg;             // ATTN: q rows, gate rows
    const __nv_bfloat16* bhi[3]; const __nv_bfloat16* blo[3];
    const float* bias[3]; float* out[3];
    int oc[3]; int ldc[3]; int act[3]; int sdinv[3];
};

#define SA 136                       // smem row stride in bf16 elems (272B)
#define SM_TILE (128 * SA * 2)       // 34816 bytes per tile image
#define OFF_A_HI 0
#define OFF_A_LO SM_TILE
#define OFF_B(buf, img) ((uint32_t)(2 + (buf) * 2 + (img)) * SM_TILE)
#define SMEM_TOTAL (6 * SM_TILE)     // 208896 bytes

__global__ __launch_bounds__(512, 1) void gemm_tc(TCParams p)
{
    extern __shared__ __align__(16) char smem[];
    uint32_t sb = smem_u32(smem);
    int t = threadIdx.x;
    int lane = t & 31, wid = t >> 5;
    int wm = wid >> 2, wn = wid & 3;       // warp grid 4x4 -> warp tile 32x32
    int row0 = blockIdx.x * 128;

    // ---- A via cp.async if pre-split ----
    if (p.amode == AM_BF16) {
        const char* ah = (const char*)(p.Ahi + (size_t)row0 * 128);
        const char* al = (const char*)(p.Alo + (size_t)row0 * 128);
#pragma unroll
        for (int i = 0; i < 4; i++) {
            int idx = i * 512 + t;               // 2048 chunks of 16B per image
            int r = idx >> 4, c8 = (idx & 15) * 8;
            uint32_t boff = (uint32_t)r * (SA * 2) + c8 * 2;
            cpa16(sb + OFF_A_HI + boff, ah + (size_t)idx * 16);
            cpa16(sb + OFF_A_LO + boff, al + (size_t)idx * 16);
        }
    }

    // ---- prefetch B0 via cp.async ----
    {
        const char* sh = (const char*)p.bhi[0];
        const char* sl = (const char*)p.blo[0];
#pragma unroll
        for (int i = 0; i < 4; i++) {
            int idx = i * 512 + t;
            int r = idx >> 4, c8 = (idx & 15) * 8;
            uint32_t boff = (uint32_t)r * (SA * 2) + c8 * 2;
            cpa16(sb + OFF_B(0, 0) + boff, sh + (size_t)idx * 16);
            cpa16(sb + OFF_B(0, 1) + boff, sl + (size_t)idx * 16);
        }
        CPA_COMMIT();
    }

    // ---- A load (+ optional fused row transform) + split to bf16 hi/lo ----
    if (p.amode != AM_BF16) {
#pragma unroll
        for (int i = 0; i < 8; i++) {
            int r = i * 16 + wid;
            int gr = row0 + r;
            int c0 = lane * 4;
            float4 v = make_float4(0.f, 0.f, 0.f, 0.f);
            if (gr < p.nrows) v = *(const float4*)(p.A + (size_t)gr * 128 + c0);

            if (p.amode == AM_LN) {
                float s1 = v.x + v.y + v.z + v.w;
                float s2 = v.x * v.x + v.y * v.y + v.z * v.z + v.w * v.w;
                s1 = wsumf(s1); s2 = wsumf(s2);
                float mu = s1 * (1.f / 128.f);
                float var = s2 * (1.f / 128.f) - mu * mu;
                float rs = rsqrtf(var + 1e-5f);
                v.x = (v.x - mu) * rs * p.lng[c0 + 0] + p.lnb[c0 + 0];
                v.y = (v.y - mu) * rs * p.lng[c0 + 1] + p.lnb[c0 + 1];
                v.z = (v.z - mu) * rs * p.lng[c0 + 2] + p.lnb[c0 + 2];
                v.w = (v.w - mu) * rs * p.lng[c0 + 3] + p.lnb[c0 + 3];
            } else if (p.amode == AM_ATTN) {
                float4 qv = make_float4(0, 0, 0, 0), hv = qv;
                if (gr < p.nrows) {
                    qv = *(const float4*)(p.q  + (size_t)gr * 128 + c0);
                    hv = *(const float4*)(p.hg + (size_t)gr * 128 + c0);
                }
                float4 ksv = *(const float4*)(g_kvs + 16384 + c0);
                float den = qv.x * ksv.x + qv.y * ksv.y + qv.z * ksv.z + qv.w * ksv.w;
                den = wsumf(den);
                float inv = 1.f / (den + 1e-6f);
                v.x *= inv; v.y *= inv; v.z *= inv; v.w *= inv;
                float s1 = v.x + v.y + v.z + v.w;
                float s2 = v.x * v.x + v.y * v.y + v.z * v.z + v.w * v.w;
                s1 = wsumf(s1); s2 = wsumf(s2);
                float mu = s1 * (1.f / 128.f);
                float var = s2 * (1.f / 128.f) - mu * mu;
                float rs = rsqrtf(var + 1e-5f);
                v.x = ((v.x - mu) * rs * p.lng[c0 + 0] + p.lnb[c0 + 0]) * (hv.x + 0.9f);
                v.y = ((v.y - mu) * rs * p.lng[c0 + 1] + p.lnb[c0 + 1]) * (hv.y + 0.9f);
                v.z = ((v.z - mu) * rs * p.lng[c0 + 2] + p.lnb[c0 + 2]) * (hv.z + 0.9f);
                v.w = ((v.w - mu) * rs * p.lng[c0 + 3] + p.lnb[c0 + 3]) * (hv.w + 0.9f);
            }

            uint32_t h0, h1, l0, l1;
            splitpack(v.x, v.y, h0, l0);
            splitpack(v.z, v.w, h1, l1);
            uint32_t boff = (uint32_t)r * (SA * 2) + (uint32_t)c0 * 2;
            *(uint2*)(smem + OFF_A_HI + boff) = make_uint2(h0, h1);
            *(uint2*)(smem + OFF_A_LO + boff) = make_uint2(l0, l1);
        }
    }
    CPA_WAIT0();
    __syncthreads();

    int g = lane >> 3, l7 = lane & 7;
    uint32_t a_row  = (uint32_t)(wm * 32 + (g & 1) * 8 + l7);
    uint32_t a_coff = (uint32_t)((g >> 1) * 8);
    uint32_t b_row  = (uint32_t)(wn * 32 + (g >> 1) * 8 + l7);
    uint32_t b_coff = (uint32_t)((g & 1) * 8);

    for (int j = 0; j < p.nout; j++) {
        if (j + 1 < p.nout) {
            const char* sh = (const char*)p.bhi[j + 1];
            const char* sl = (const char*)p.blo[j + 1];
            uint32_t bufh = OFF_B((j + 1) & 1, 0), bufl = OFF_B((j + 1) & 1, 1);
#pragma unroll
            for (int i = 0; i < 4; i++) {
                int idx = i * 512 + t;
                int r = idx >> 4, c8 = (idx & 15) * 8;
                uint32_t boff = (uint32_t)r * (SA * 2) + c8 * 2;
                cpa16(sb + bufh + boff, sh + (size_t)idx * 16);
                cpa16(sb + bufl + boff, sl + (size_t)idx * 16);
            }
            CPA_COMMIT();
        }

        float acc[2][4][4];
#pragma unroll
        for (int mt = 0; mt < 2; mt++)
#pragma unroll
            for (int nt = 0; nt < 4; nt++)
#pragma unroll
                for (int q2 = 0; q2 < 4; q2++) acc[mt][nt][q2] = 0.f;

        uint32_t obh = OFF_B(j & 1, 0), obl = OFF_B(j & 1, 1);
#pragma unroll
        for (int ks = 0; ks < 8; ks++) {
            uint32_t ah[2][4], al[2][4];
#pragma unroll
            for (int mt = 0; mt < 2; mt++) {
                uint32_t off = ((a_row + mt * 16) * SA + ks * 16 + a_coff) * 2;
                ldmat4(ah[mt][0], ah[mt][1], ah[mt][2], ah[mt][3], sb + OFF_A_HI + off);
                ldmat4(al[mt][0], al[mt][1], al[mt][2], al[mt][3], sb + OFF_A_LO + off);
            }
            uint32_t bh[4][2], bl[4][2];
#pragma unroll
            for (int np = 0; np < 2; np++) {
                uint32_t off = ((b_row + np * 16) * SA + ks * 16 + b_coff) * 2;
                ldmat4(bh[2 * np][0], bh[2 * np][1], bh[2 * np + 1][0], bh[2 * np + 1][1],
                       sb + obh + off);
                ldmat4(bl[2 * np][0], bl[2 * np][1], bl[2 * np + 1][0], bl[2 * np + 1][1],
                       sb + obl + off);
            }
#pragma unroll
            for (int mt = 0; mt < 2; mt++)
#pragma unroll
                for (int nt = 0; nt < 4; nt++) {
                    mma16816(acc[mt][nt], ah[mt], bh[nt]);
                    mma16816(acc[mt][nt], ah[mt], bl[nt]);
                    mma16816(acc[mt][nt], al[mt], bh[nt]);
                }
        }

        // ---- epilogue (register-only) ----
        {
            const float* bs = p.bias[j];
            float* outp = p.out[j];
            int oc = p.oc[j], ldc = p.ldc[j], act = p.act[j], sdv = p.sdinv[j];
#pragma unroll
            for (int mt = 0; mt < 2; mt++) {
                int r0 = row0 + wm * 32 + mt * 16 + (lane >> 2);
                int r1 = r0 + 8;
                float sc0 = 1.f, sc1 = 1.f;
                if (sdv) {
                    if (r0 < p.nrows) sc0 = g_dinv[r0];
                    if (r1 < p.nrows) sc1 = g_dinv[r1];
                }
#pragma unroll
                for (int nt = 0; nt < 4; nt++) {
                    int c = wn * 32 + nt * 8 + (lane & 3) * 2;
                    if (c >= oc) continue;
                    float b0 = bs ? bs[c] : 0.f;
                    float b1 = bs ? bs[c + 1] : 0.f;
                    float d0 = acc[mt][nt][0] + b0;
                    float d1 = acc[mt][nt][1] + b1;
                    float d2 = acc[mt][nt][2] + b0;
                    float d3 = acc[mt][nt][3] + b1;
                    if (act == ACT_RELU) {
                        d0 = fmaxf(d0, 0.f); d1 = fmaxf(d1, 0.f);
                        d2 = fmaxf(d2, 0.f); d3 = fmaxf(d3, 0.f);
                    } else if (act == ACT_SIGM) {
                        d0 = 1.f / (1.f + expf(-d0));
                        d1 = 1.f / (1.f + expf(-d1));
                        d2 = 1.f / (1.f + expf(-d2));
                        d3 = 1.f / (1.f + expf(-d3));
                    }
                    d0 *= sc0; d1 *= sc0; d2 *= sc1; d3 *= sc1;
                    if (r0 < p.nrows) *(float2*)(outp + (size_t)r0 * ldc + c) = make_float2(d0, d1);
                    if (r1 < p.nrows) *(float2*)(outp + (size_t)r1 * ldc + c) = make_float2(d2, d3);
                }
            }
        }

        if (j + 1 < p.nout) {
            CPA_WAIT0();
            __syncthreads();
        }
    }
}

// ------------------- edge dtype detect + CSR build -------------------
__global__ void detect_k(const int* __restrict__ w, int nwords)
{
    __shared__ int any;
    if (threadIdx.x == 0) any = 0;
    __syncthreads();
    int npairs = min(nwords >> 1, 2048);
    for (int i = threadIdx.x; i < npairs; i += blockDim.x)
        if (w[2 * i + 1] != 0) atomicOr(&any, 1);
    __syncthreads();
    if (threadIdx.x == 0) g_is64 = (any == 0) ? 1 : 0;
}

__device__ __forceinline__ int edge_at(const void* ei, long long idx)
{
    return g_is64 ? (int)((const long long*)ei)[idx] : ((const int*)ei)[idx];
}

__global__ void hist_k(const void* __restrict__ ei, long long eoff, int ne)
{
    for (int e = blockIdx.x * blockDim.x + threadIdx.x; e < ne; e += gridDim.x * blockDim.x)
        atomicAdd(&g_deg[edge_at(ei, eoff + e)], 1);
}

__global__ void scan1(int n)
{
    __shared__ int wsum[32];
    int t = threadIdx.x;
    int idx = blockIdx.x * 4096 + t * 4;
    int v0 = (idx + 0 < n) ? g_deg[idx + 0] : 0;
    int v1 = (idx + 1 < n) ? g_deg[idx + 1] : 0;
    int v2 = (idx + 2 < n) ? g_deg[idx + 2] : 0;
    int v3 = (idx + 3 < n) ? g_deg[idx + 3] : 0;
    if (idx + 0 < n) g_dinv[idx + 0] = rsqrtf((float)(v0 + 1));
    if (idx + 1 < n) g_dinv[idx + 1] = rsqrtf((float)(v1 + 1));
    if (idx + 2 < n) g_dinv[idx + 2] = rsqrtf((float)(v2 + 1));
    if (idx + 3 < n) g_dinv[idx + 3] = rsqrtf((float)(v3 + 1));
    int tsum = v0 + v1 + v2 + v3;
    int lane = t & 31, w = t >> 5;
    int inc = tsum;
#pragma unroll
    for (int o = 1; o < 32; o <<= 1) {
        int y = __shfl_up_sync(0xffffffffu, inc, o);
        if (lane >= o) inc += y;
    }
    if (lane == 31) wsum[w] = inc;
    __syncthreads();
    if (w == 0) {
        int y = wsum[lane];
#pragma unroll
        for (int o = 1; o < 32; o <<= 1) {
            int z = __shfl_up_sync(0xffffffffu, y, o);
            if (lane >= o) y += z;
        }
        wsum[lane] = y;
    }
    __syncthreads();
    int excl = inc - tsum + (w > 0 ? wsum[w - 1] : 0);
    if (idx + 0 < n) g_rowp[idx + 0] = excl;
    if (idx + 1 < n) g_rowp[idx + 1] = excl + v0;
    if (idx + 2 < n) g_rowp[idx + 2] = excl + v0 + v1;
    if (idx + 3 < n) g_rowp[idx + 3] = excl + v0 + v1 + v2;
    if (t == 0) g_bsum[blockIdx.x] = wsum[31];
}

__global__ void scan2(int nb)
{
    if (threadIdx.x == 0 && blockIdx.x == 0) {
        int s = 0;
        for (int i = 0; i < nb; i++) { int t = g_bsum[i]; g_bsum[i] = s; s += t; }
    }
}

__global__ void scan3(int n, int total)
{
    int t = threadIdx.x;
    int idx = blockIdx.x * 4096 + t * 4;
    int off = g_bsum[blockIdx.x];
#pragma unroll
    for (int j = 0; j < 4; j++)
        if (idx + j < n) g_rowp[idx + j] += off;
    if (blockIdx.x == 0 && t == 0) g_rowp[n] = total;
}

__global__ void scatter_k(const void* __restrict__ ei, long long eoff, int ne)
{
    for (int e = blockIdx.x * blockDim.x + threadIdx.x; e < ne; e += gridDim.x * blockDim.x) {
        int d = edge_at(ei, eoff + e);
        int s = edge_at(ei, e);
        int pos = g_rowp[d] + atomicAdd(&g_fill[d], 1);
        g_col[pos] = s;
    }
}

// ------------------- kv = k^T v  (fp32, atomic finalize) + fused ksum -----------
__global__ __launch_bounds__(256)
void kv_k(const float* __restrict__ kk, const float* __restrict__ vv, int n)
{
    __shared__ float ks[32][128];
    __shared__ float vs[32][128];
    int t = threadIdx.x;
    int tx = t & 15, ty = t >> 4;
    int base = blockIdx.x * 512;
    int end = min(base + 512, n);

    int kcol = t & 127, krh = (t >> 7) * 16;
    float ksacc = 0.f;

    ull acc[4][8];
#pragma unroll
    for (int i = 0; i < 4; i++)
#pragma unroll
        for (int j = 0; j < 8; j++) acc[i][j] = 0ULL;

    for (int nb = base; nb < end; nb += 32) {
#pragma unroll
        for (int q = 0; q < 4; q++) {
            int idx = t + 256 * q;
            int r = idx >> 5, c = (idx & 31) * 4;
            int gr = nb + r;
            float4 a = make_float4(0, 0, 0, 0), b = make_float4(0, 0, 0, 0);
            if (gr < n) {
                a = *(const float4*)(kk + (size_t)gr * 128 + c);
                b = *(const float4*)(vv + (size_t)gr * 128 + c);
            }
            *(float4*)&ks[r][c] = a;
            *(float4*)&vs[r][c] = b;
        }
        __syncthreads();
#pragma unroll
        for (int r = 0; r < 16; r++) ksacc += ks[krh + r][kcol];
#pragma unroll 8
        for (int nn = 0; nn < 32; nn++) {
            ull a2[4];
            a2[0] = *(const ull*)&ks[nn][ty * 8 + 0];
            a2[1] = *(const ull*)&ks[nn][ty * 8 + 2];
            a2[2] = *(const ull*)&ks[nn][ty * 8 + 4];
            a2[3] = *(const ull*)&ks[nn][ty * 8 + 6];
            float b[8];
            *(float4*)&b[0] = *(const float4*)&vs[nn][tx * 8];
            *(float4*)&b[4] = *(const float4*)&vs[nn][tx * 8 + 4];
#pragma unroll
            for (int j = 0; j < 8; j++) {
                ull bd = pk2(b[j]);
#pragma unroll
                for (int i = 0; i < 4; i++) acc[i][j] = fma2(a2[i], bd, acc[i][j]);
            }
        }
        __syncthreads();
    }
#pragma unroll
    for (int i = 0; i < 4; i++)
#pragma unroll
        for (int j = 0; j < 8; j++) {
            float lo, hi;
            upk(acc[i][j], lo, hi);
            int d = ty * 8 + 2 * i, m = tx * 8 + j;
            atomicAdd(&g_kvs[d * 128 + m], lo);
            atomicAdd(&g_kvs[(d + 1) * 128 + m], hi);
        }
    ((float*)ks)[t] = ksacc;
    __syncthreads();
    if (t < 128) atomicAdd(&g_kvs[16384 + t], ksacc + ((float*)ks)[t + 128]);
}

// ------------------- fused SpMM + GCN-layer epilogue (warp per node) ------------
// g_xw holds y = xw * dinv (pre-scaled in GEMM epilogue)
__global__ __launch_bounds__(256)
void spmm_epi(const float* __restrict__ bg,
              const float* __restrict__ bng, const float* __restrict__ bnb,
              const float* __restrict__ bnrm, const float* __restrict__ bnrv,
              const float* __restrict__ lng, const float* __restrict__ lnb,
              int n, int first, int last)
{
    int w = (blockIdx.x * blockDim.x + threadIdx.x) >> 5;
    int lane = threadIdx.x & 31;
    if (w >= n) return;
    int c0 = lane * 4;

    // 4 independent accumulators for MLP on the gather
    float4 a0 = *(const float4*)(g_xw + (size_t)w * 128 + c0);   // self term y_w
    float4 a1 = make_float4(0, 0, 0, 0);
    float4 a2 = make_float4(0, 0, 0, 0);
    float4 a3 = make_float4(0, 0, 0, 0);
    int e0 = g_rowp[w], e1 = g_rowp[w + 1];
    int e = e0;
    for (; e + 4 <= e1; e += 4) {
        int ca = g_col[e], cb = g_col[e + 1], cc = g_col[e + 2], cd = g_col[e + 3];
        float4 va = *(const float4*)(g_xw + (size_t)ca * 128 + c0);
        float4 vb = *(const float4*)(g_xw + (size_t)cb * 128 + c0);
        float4 vc = *(const float4*)(g_xw + (size_t)cc * 128 + c0);
        float4 vd = *(const float4*)(g_xw + (size_t)cd * 128 + c0);
        a0.x += va.x; a0.y += va.y; a0.z += va.z; a0.w += va.w;
        a1.x += vb.x; a1.y += vb.y; a1.z += vb.z; a1.w += vb.w;
        a2.x += vc.x; a2.y += vc.y; a2.z += vc.z; a2.w += vc.w;
        a3.x += vd.x; a3.y += vd.y; a3.z += vd.z; a3.w += vd.w;
    }
    for (; e < e1; e++) {
        int c = g_col[e];
        float4 v = *(const float4*)(g_xw + (size_t)c * 128 + c0);
        a1.x += v.x; a1.y += v.y; a1.z += v.z; a1.w += v.w;
    }
    float4 acc;
    acc.x = (a0.x + a1.x) + (a2.x + a3.x);
    acc.y = (a0.y + a1.y) + (a2.y + a3.y);
    acc.z = (a0.z + a1.z) + (a2.z + a3.z);
    acc.w = (a0.w + a1.w) + (a2.w + a3.w);

    float di = g_dinv[w];
    float4 lv = *(const float4*)(g_lin + (size_t)w * 128 + c0);
    float4 xv;
    xv.x = acc.x * di + bg[c0 + 0] + lv.x;
    xv.y = acc.y * di + bg[c0 + 1] + lv.y;
    xv.z = acc.z * di + bg[c0 + 2] + lv.z;
    xv.w = acc.w * di + bg[c0 + 3] + lv.w;
#pragma unroll
    for (int j = 0; j < 4; j++) {
        float s = bng[c0 + j] * rsqrtf(bnrv[c0 + j] + 1e-5f);
        float* p = &xv.x + j;
        *p = fmaxf((*p - bnrm[c0 + j]) * s + bnb[c0 + j], 0.f);
    }
    float4 hv = *(const float4*)(g_h + (size_t)w * 128 + c0);
    float4 tv;
    tv.x = hv.x * xv.x; tv.y = hv.y * xv.y; tv.z = hv.z * xv.z; tv.w = hv.w * xv.w;
    float s1 = tv.x + tv.y + tv.z + tv.w;
    float s2 = tv.x * tv.x + tv.y * tv.y + tv.z * tv.z + tv.w * tv.w;
    s1 = wsumf(s1); s2 = wsumf(s2);
    float mu = s1 * (1.f / 128.f);
    float var = s2 * (1.f / 128.f) - mu * mu;
    float rs = rsqrtf(var + 1e-5f);
#pragma unroll
    for (int j = 0; j < 4; j++) {
        float* pt = &tv.x + j;
        float* px = &xv.x + j;
        float y = (*pt - mu) * rs * lng[c0 + j] + lnb[c0 + j];
        *px = 0.1f * y + 0.9f * (*px);
    }
    float4 xl = make_float4(0, 0, 0, 0);
    if (!first) xl = *(const float4*)(g_xloc + (size_t)w * 128 + c0);
    xl.x += xv.x; xl.y += xv.y; xl.z += xv.z; xl.w += xv.w;
    *(float4*)(g_xloc + (size_t)w * 128 + c0) = xl;
    if (!last) {
        // emit next layer's A as split bf16
        uint32_t h0, h1, l0, l1;
        splitpack(xv.x, xv.y, h0, l0);
        splitpack(xv.z, xv.w, h1, l1);
        *(uint2*)(g_xsh + (size_t)w * 128 + c0) = make_uint2(h0, h1);
        *(uint2*)(g_xsl + (size_t)w * 128 + c0) = make_uint2(l0, l1);
    }
}

// ------------------- host orchestration -------------------
static inline void fill1(TCParams& p, int i, const __nv_bfloat16* bh, const __nv_bfloat16* bl,
                         const float* bias, float* out, int oc, int ldc, int act, int sdv = 0)
{
    p.bhi[i] = bh; p.blo[i] = bl; p.bias[i] = bias; p.out[i] = out;
    p.oc[i] = oc; p.ldc[i] = ldc; p.act[i] = act; p.sdinv[i] = sdv;
}

extern "C" void kernel_launch(void* const* d_in, const int* in_sizes, int n_in,
                              void* d_out, int out_size)
{
    const float* in_x  = (const float*)d_in[0];
    const void*  ei    = d_in[1];
    const float* Wh    = (const float*)d_in[2];
    const float* bh    = (const float*)d_in[3];
    const float* Wg    = (const float*)d_in[4];
    const float* bg    = (const float*)d_in[5];
    const float* Wl    = (const float*)d_in[6];
    const float* bl    = (const float*)d_in[7];
    const float* ln_g  = (const float*)d_in[8];
    const float* ln_b  = (const float*)d_in[9];
    const float* bn_g  = (const float*)d_in[10];
    const float* bn_b  = (const float*)d_in[11];
    const float* bn_rm = (const float*)d_in[12];
    const float* bn_rv = (const float*)d_in[13];
    const float* gWh   = (const float*)d_in[14];
    const float* gbh   = (const float*)d_in[15];
    const float* gWk   = (const float*)d_in[16];
    const float* gWv   = (const float*)d_in[17];
    const float* gln_g = (const float*)d_in[18];
    const float* gln_b = (const float*)d_in[19];
    const float* gWo   = (const float*)d_in[20];
    const float* gbo   = (const float*)d_in[21];
    const float* f_ln_g = (const float*)d_in[22];
    const float* f_ln_b = (const float*)d_in[23];
    const float* Wp    = (const float*)d_in[24];
    const float* bp    = (const float*)d_in[25];

    int n  = in_sizes[0] / 128;
    int ne = in_sizes[1] / 2;

    float *ph, *pxw, *plin, *pxloc, *pxg, *pk, *pkvs;
    __nv_bfloat16 *pBhi, *pBlo, *pxsh, *pxsl;
    int *pdeg, *pfill;
    cudaGetSymbolAddress((void**)&ph, g_h);
    cudaGetSymbolAddress((void**)&pxw, g_xw);
    cudaGetSymbolAddress((void**)&plin, g_lin);
    cudaGetSymbolAddress((void**)&pxloc, g_xloc);
    cudaGetSymbolAddress((void**)&pxg, g_xg);
    cudaGetSymbolAddress((void**)&pk, g_k);
    cudaGetSymbolAddress((void**)&pkvs, g_kvs);
    cudaGetSymbolAddress((void**)&pdeg, g_deg);
    cudaGetSymbolAddress((void**)&pfill, g_fill);
    cudaGetSymbolAddress((void**)&pBhi, g_Bhi);
    cudaGetSymbolAddress((void**)&pBlo, g_Blo);
    cudaGetSymbolAddress((void**)&pxsh, g_xsh);
    cudaGetSymbolAddress((void**)&pxsl, g_xsl);

    cudaFuncSetAttribute(gemm_tc, cudaFuncAttributeMaxDynamicSharedMemorySize, SMEM_TOTAL);

    int gg = (n + 127) / 128;
    int wg = (n * 32 + 255) / 256;
    int nblk = (n + 4095) / 4096;

    cudaMemsetAsync(pdeg, 0, (size_t)n * 4);
    cudaMemsetAsync(pfill, 0, (size_t)n * 4);

    prep_all<<<(30 * 16384 + 255) / 256, 256>>>(Wh, Wg, Wl, gWh, gWk, gWv, gWo, Wp, pBhi, pBlo);
    detect_k<<<1, 256>>>((const int*)ei, ne * 2);
    hist_k<<<2048, 256>>>(ei, (long long)ne, ne);
    scan1<<<nblk, 1024>>>(n);
    scan2<<<1, 32>>>(nblk);

    // first GEMM (layer 1) — A = in_x (fp32 path)
    {
        TCParams p = {};
        p.A = in_x; p.nrows = n; p.nout = 3; p.amode = AM_PLAIN;
        fill1(p, 0, pBhi + (size_t)0 * 16384,  pBlo + (size_t)0 * 16384,  bh, ph,   128, 128, ACT_RELU);
        fill1(p, 1, pBhi + (size_t)7 * 16384,  pBlo + (size_t)7 * 16384,  nullptr, pxw,  128, 128, ACT_NONE, 1);
        fill1(p, 2, pBhi + (size_t)14 * 16384, pBlo + (size_t)14 * 16384, bl, plin, 128, 128, ACT_NONE);
        gemm_tc<<<gg, 512, SMEM_TOTAL>>>(p);
    }

    scan3<<<nblk, 1024>>>(n, ne);
    scatter_k<<<2048, 256>>>(ei, (long long)ne, ne);

    spmm_epi<<<wg, 256>>>(bg, bn_g, bn_b, bn_rm, bn_rv, ln_g, ln_b, n, 1, 0);

    for (int i = 1; i < 7; i++) {
        TCParams p = {};
        p.nrows = n; p.nout = 3; p.amode = AM_BF16;
        p.Ahi = pxsh; p.Alo = pxsl;
        fill1(p, 0, pBhi + (size_t)i * 16384,        pBlo + (size_t)i * 16384,        bh + i * 128, ph,   128, 128, ACT_RELU);
        fill1(p, 1, pBhi + (size_t)(7 + i) * 16384,  pBlo + (size_t)(7 + i) * 16384,  nullptr,      pxw,  128, 128, ACT_NONE, 1);
        fill1(p, 2, pBhi + (size_t)(14 + i) * 16384, pBlo + (size_t)(14 + i) * 16384, bl + i * 128, plin, 128, 128, ACT_NONE);
        gemm_tc<<<gg, 512, SMEM_TOTAL>>>(p);
        spmm_epi<<<wg, 256>>>(bg + i * 128, bn_g + i * 128, bn_b + i * 128,
                              bn_rm + i * 128, bn_rv + i * 128,
                              ln_g + i * 128, ln_b + i * 128, n, 0, i == 6);
    }

    // global attention (LN fused into first projection GEMM; attn_epi fused into out-GEMM)
    for (int j = 0; j < 2; j++) {
        {
            TCParams p = {};
            p.nrows = n; p.nout = 3;
            if (j == 0) { p.A = pxloc; p.amode = AM_LN; p.lng = f_ln_g; p.lnb = f_ln_b; }
            else        { p.A = pxg;   p.amode = AM_PLAIN; }
            fill1(p, 0, pBhi + (size_t)(21 + j) * 16384, pBlo + (size_t)(21 + j) * 16384, gbh + j * 128, ph,  128, 128, ACT_NONE);
            fill1(p, 1, pBhi + (size_t)(23 + j) * 16384, pBlo + (size_t)(23 + j) * 16384, nullptr,       pk,  128, 128, ACT_SIGM);
            fill1(p, 2, pBhi + (size_t)(25 + j) * 16384, pBlo + (size_t)(25 + j) * 16384, nullptr,       pxw, 128, 128, ACT_NONE);
            gemm_tc<<<gg, 512, SMEM_TOTAL>>>(p);
        }
        cudaMemsetAsync(pkvs, 0, (128 * 128 + 128) * 4);
        kv_k<<<(n + 511) / 512, 256>>>(pk, pxw, n);
        prep_kv<<<(16384 + 255) / 256, 256>>>(pBhi, pBlo);
        {
            TCParams p = {};
            p.A = pk; p.nrows = n; p.nout = 1; p.amode = AM_PLAIN;
            fill1(p, 0, pBhi + (size_t)30 * 16384, pBlo + (size_t)30 * 16384, nullptr, plin, 128, 128, ACT_NONE);
            gemm_tc<<<gg, 512, SMEM_TOTAL>>>(p);
        }
        {
            // out-GEMM with fused attention epilogue as A-transform
            TCParams p = {};
            p.A = plin; p.nrows = n; p.nout = 1; p.amode = AM_ATTN;
            p.lng = gln_g + j * 128; p.lnb = gln_b + j * 128;
            p.q = pk; p.hg = ph;
            fill1(p, 0, pBhi + (size_t)(27 + j) * 16384, pBlo + (size_t)(27 + j) * 16384, gbo + j * 128, pxg, 128, 128, ACT_RELU);
            gemm_tc<<<gg, 512, SMEM_TOTAL>>>(p);
        }
    }

    // final projection (oc=40)
    {
        TCParams p = {};
        p.A = pxg; p.nrows = n; p.nout = 1; p.amode = AM_PLAIN;
        fill1(p, 0, pBhi + (size_t)29 * 16384, pBlo + (size_t)29 * 16384, bp, (float*)d_out, 40, 40, ACT_NONE);
        gemm_tc<<<gg, 512, SMEM_TOTAL>>>(p);
    }
}

// round 14
// speedup vs baseline: 1.4905x; 1.4905x over previous
#include <cuda_runtime.h>
#include <cuda_bf16.h>
#include <cstddef>
#include <cstdint>

#define NMAX 100000
#define EMAX 1600000
#define CH 128

typedef unsigned long long ull;

// ------------------- device scratch (no allocations allowed) -------------------
__device__ __align__(16) float g_x   [NMAX * CH];
__device__ __align__(16) float g_h   [NMAX * CH];
__device__ __align__(16) float g_xw  [NMAX * CH];   // GCN: y = xw*dinv ; attn: v
__device__ __align__(16) float g_lin [NMAX * CH];   // also num
__device__ __align__(16) float g_xloc[NMAX * CH];
__device__ __align__(16) float g_xg  [NMAX * CH];
__device__ __align__(16) float g_k   [NMAX * CH];
__device__ __align__(16) float g_dinv[NMAX];
__device__ int   g_deg [NMAX];
__device__ int   g_rowp[NMAX + 1];
__device__ int   g_fill[NMAX];
__device__ int   g_col [EMAX];
__device__ int   g_bsum[64];
__device__ int   g_is64;
// kv [128][128] followed by ksum[128]
__device__ __align__(16) float g_kvs [CH * CH + CH];
// pre-split bf16 weights, row-major [n=128][k=128] per slot (slot 30 = kv)
__device__ __align__(16) __nv_bfloat16 g_Bhi[31 * 16384];
__device__ __align__(16) __nv_bfloat16 g_Blo[31 * 16384];

// ------------------- f32x2 helpers (kv kernel) -------------------
__device__ __forceinline__ ull fma2(ull a, ull b, ull c) {
    ull d; asm("fma.rn.f32x2 %0, %1, %2, %3;" : "=l"(d) : "l"(a), "l"(b), "l"(c));
    return d;
}
__device__ __forceinline__ ull pk2(float v) {
    ull r; asm("mov.b64 %0, {%1, %1};" : "=l"(r) : "f"(v)); return r;
}
__device__ __forceinline__ void upk(ull v, float& lo, float& hi) {
    asm("mov.b64 {%0, %1}, %2;" : "=f"(lo), "=f"(hi) : "l"(v));
}
__device__ __forceinline__ float wsumf(float v) {
#pragma unroll
    for (int o = 16; o; o >>= 1) v += __shfl_xor_sync(0xffffffffu, v, o);
    return v;
}

// ------------------- mma / cp.async helpers -------------------
__device__ __forceinline__ uint32_t smem_u32(const void* p) {
    uint32_t a;
    asm("{ .reg .u64 t; cvta.to.shared.u64 t, %1; cvt.u32.u64 %0, t; }" : "=r"(a) : "l"(p));
    return a;
}
__device__ __forceinline__ void ldmat4(uint32_t& r0, uint32_t& r1, uint32_t& r2, uint32_t& r3,
                                       uint32_t addr) {
    asm volatile("ldmatrix.sync.aligned.m8n8.x4.shared.b16 {%0,%1,%2,%3}, [%4];"
                 : "=r"(r0), "=r"(r1), "=r"(r2), "=r"(r3) : "r"(addr));
}
__device__ __forceinline__ void mma16816(float* d, const uint32_t* a, const uint32_t* b) {
    asm volatile(
        "mma.sync.aligned.m16n8k16.row.col.f32.bf16.bf16.f32 "
        "{%0,%1,%2,%3}, {%4,%5,%6,%7}, {%8,%9}, {%0,%1,%2,%3};"
        : "+f"(d[0]), "+f"(d[1]), "+f"(d[2]), "+f"(d[3])
        : "r"(a[0]), "r"(a[1]), "r"(a[2]), "r"(a[3]), "r"(b[0]), "r"(b[1]));
}
__device__ __forceinline__ void cpa16(uint32_t dst, const void* src) {
    asm volatile("cp.async.cg.shared.global [%0], [%1], 16;" :: "r"(dst), "l"(src));
}
#define CPA_COMMIT() asm volatile("cp.async.commit_group;" ::: "memory")
#define CPA_WAIT0()  asm volatile("cp.async.wait_group 0;" ::: "memory")

__device__ __forceinline__ void splitpack(float a, float b, uint32_t& hw, uint32_t& lw) {
    __nv_bfloat16 ha = __float2bfloat16(a), hb = __float2bfloat16(b);
    float ra = a - __bfloat162float(ha), rb = b - __bfloat162float(hb);
    __nv_bfloat16 la = __float2bfloat16(ra), lb = __float2bfloat16(rb);
    __nv_bfloat162 hv(ha, hb), lv(la, lb);
    hw = *(uint32_t*)&hv; lw = *(uint32_t*)&lv;
}

// ------------------- weight prep -------------------
__global__ void prep_all(const float* __restrict__ Wh, const float* __restrict__ Wg,
                         const float* __restrict__ Wl, const float* __restrict__ gWh,
                         const float* __restrict__ gWk, const float* __restrict__ gWv,
                         const float* __restrict__ gWo, const float* __restrict__ Wp,
                         __nv_bfloat16* __restrict__ dhi, __nv_bfloat16* __restrict__ dlo)
{
    int idx = blockIdx.x * blockDim.x + threadIdx.x;
    if (idx >= 30 * 16384) return;
    int s = idx >> 14;
    const float* src; int m; int oc = 128;
    if      (s < 7)  { src = Wh;  m = s; }
    else if (s < 14) { src = Wg;  m = s - 7; }
    else if (s < 21) { src = Wl;  m = s - 14; }
    else if (s < 23) { src = gWh; m = s - 21; }
    else if (s < 25) { src = gWk; m = s - 23; }
    else if (s < 27) { src = gWv; m = s - 25; }
    else if (s < 29) { src = gWo; m = s - 27; }
    else             { src = Wp;  m = 0; oc = 40; }
    int rem = idx & 16383, o = rem >> 7, k = rem & 127;
    float v = (o < oc) ? src[(size_t)m * oc * 128 + (size_t)o * 128 + k] : 0.f;
    __nv_bfloat16 hi = __float2bfloat16(v);
    dhi[idx] = hi;
    dlo[idx] = __float2bfloat16(v - __bfloat162float(hi));
}

__global__ void prep_kv(__nv_bfloat16* __restrict__ dhi, __nv_bfloat16* __restrict__ dlo)
{
    int idx = blockIdx.x * blockDim.x + threadIdx.x;
    if (idx >= 16384) return;
    int o = idx >> 7, k = idx & 127;
    float v = g_kvs[k * 128 + o];
    __nv_bfloat16 hi = __float2bfloat16(v);
    dhi[(size_t)30 * 16384 + idx] = hi;
    dlo[(size_t)30 * 16384 + idx] = __float2bfloat16(v - __bfloat162float(hi));
}

// ------------------- tensor-core GEMM: up to 3 products sharing A -------------------
#define ACT_NONE 0
#define ACT_RELU 1
#define ACT_SIGM 2

#define AM_PLAIN 0
#define AM_LN    1
#define AM_ATTN  2

struct TCParams {
    const float* A; int nrows; int nout; int amode;
    const float* lng; const float* lnb;          // LN / ATTN params
    const float* q; const float* hg;             // ATTN: q rows, gate rows
    const __nv_bfloat16* bhi[3]; const __nv_bfloat16* blo[3];
    const float* bias[3]; float* out[3];
    int oc[3]; int ldc[3]; int act[3]; int sdinv[3];
};

#define SA 136                       // smem row stride in bf16 elems (272B)
#define SM_TILE (128 * SA * 2)       // 34816 bytes per tile image
#define OFF_A_HI 0
#define OFF_A_LO SM_TILE
#define OFF_B(buf, img) ((uint32_t)(2 + (buf) * 2 + (img)) * SM_TILE)
#define SMEM_TOTAL (6 * SM_TILE)     // 208896 bytes

__global__ __launch_bounds__(512, 1) void gemm_tc(TCParams p)
{
    extern __shared__ __align__(16) char smem[];
    uint32_t sb = smem_u32(smem);
    int t = threadIdx.x;
    int lane = t & 31, wid = t >> 5;
    int wm = wid >> 2, wn = wid & 3;       // warp grid 4x4 -> warp tile 32x32
    int row0 = blockIdx.x * 128;

    // ---- prefetch B0 via cp.async (overlaps A conversion) ----
    {
        const char* sh = (const char*)p.bhi[0];
        const char* sl = (const char*)p.blo[0];
#pragma unroll
        for (int i = 0; i < 4; i++) {
            int idx = i * 512 + t;               // 2048 chunks of 16B per image
            int r = idx >> 4, c8 = (idx & 15) * 8;
            uint32_t boff = (uint32_t)r * (SA * 2) + c8 * 2;
            cpa16(sb + OFF_B(0, 0) + boff, sh + (size_t)idx * 16);
            cpa16(sb + OFF_B(0, 1) + boff, sl + (size_t)idx * 16);
        }
        CPA_COMMIT();
    }

    // ---- A load (+ optional fused row transform) + split to bf16 hi/lo ----
    // each warp owns whole rows: iteration i covers row r = i*16 + wid
#pragma unroll
    for (int i = 0; i < 8; i++) {
        int r = i * 16 + wid;
        int gr = row0 + r;
        int c0 = lane * 4;
        float4 v = make_float4(0.f, 0.f, 0.f, 0.f);
        if (gr < p.nrows) v = *(const float4*)(p.A + (size_t)gr * 128 + c0);

        if (p.amode == AM_LN) {
            float s1 = v.x + v.y + v.z + v.w;
            float s2 = v.x * v.x + v.y * v.y + v.z * v.z + v.w * v.w;
            s1 = wsumf(s1); s2 = wsumf(s2);
            float mu = s1 * (1.f / 128.f);
            float var = s2 * (1.f / 128.f) - mu * mu;
            float rs = rsqrtf(var + 1e-5f);
            v.x = (v.x - mu) * rs * p.lng[c0 + 0] + p.lnb[c0 + 0];
            v.y = (v.y - mu) * rs * p.lng[c0 + 1] + p.lnb[c0 + 1];
            v.z = (v.z - mu) * rs * p.lng[c0 + 2] + p.lnb[c0 + 2];
            v.w = (v.w - mu) * rs * p.lng[c0 + 3] + p.lnb[c0 + 3];
        } else if (p.amode == AM_ATTN) {
            float4 qv = make_float4(0, 0, 0, 0), hv = qv;
            if (gr < p.nrows) {
                qv = *(const float4*)(p.q  + (size_t)gr * 128 + c0);
                hv = *(const float4*)(p.hg + (size_t)gr * 128 + c0);
            }
            float4 ksv = *(const float4*)(g_kvs + 16384 + c0);
            float den = qv.x * ksv.x + qv.y * ksv.y + qv.z * ksv.z + qv.w * ksv.w;
            den = wsumf(den);
            float inv = 1.f / (den + 1e-6f);
            v.x *= inv; v.y *= inv; v.z *= inv; v.w *= inv;
            float s1 = v.x + v.y + v.z + v.w;
            float s2 = v.x * v.x + v.y * v.y + v.z * v.z + v.w * v.w;
            s1 = wsumf(s1); s2 = wsumf(s2);
            float mu = s1 * (1.f / 128.f);
            float var = s2 * (1.f / 128.f) - mu * mu;
            float rs = rsqrtf(var + 1e-5f);
            v.x = ((v.x - mu) * rs * p.lng[c0 + 0] + p.lnb[c0 + 0]) * (hv.x + 0.9f);
            v.y = ((v.y - mu) * rs * p.lng[c0 + 1] + p.lnb[c0 + 1]) * (hv.y + 0.9f);
            v.z = ((v.z - mu) * rs * p.lng[c0 + 2] + p.lnb[c0 + 2]) * (hv.z + 0.9f);
            v.w = ((v.w - mu) * rs * p.lng[c0 + 3] + p.lnb[c0 + 3]) * (hv.w + 0.9f);
        }

        uint32_t h0, h1, l0, l1;
        splitpack(v.x, v.y, h0, l0);
        splitpack(v.z, v.w, h1, l1);
        uint32_t boff = (uint32_t)r * (SA * 2) + (uint32_t)c0 * 2;
        *(uint2*)(smem + OFF_A_HI + boff) = make_uint2(h0, h1);
        *(uint2*)(smem + OFF_A_LO + boff) = make_uint2(l0, l1);
    }
    CPA_WAIT0();
    __syncthreads();

    int g = lane >> 3, l7 = lane & 7;
    uint32_t a_row  = (uint32_t)(wm * 32 + (g & 1) * 8 + l7);
    uint32_t a_coff = (uint32_t)((g >> 1) * 8);
    uint32_t b_row  = (uint32_t)(wn * 32 + (g >> 1) * 8 + l7);
    uint32_t b_coff = (uint32_t)((g & 1) * 8);

    for (int j = 0; j < p.nout; j++) {
        if (j + 1 < p.nout) {
            const char* sh = (const char*)p.bhi[j + 1];
            const char* sl = (const char*)p.blo[j + 1];
            uint32_t bufh = OFF_B((j + 1) & 1, 0), bufl = OFF_B((j + 1) & 1, 1);
#pragma unroll
            for (int i = 0; i < 4; i++) {
                int idx = i * 512 + t;
                int r = idx >> 4, c8 = (idx & 15) * 8;
                uint32_t boff = (uint32_t)r * (SA * 2) + c8 * 2;
                cpa16(sb + bufh + boff, sh + (size_t)idx * 16);
                cpa16(sb + bufl + boff, sl + (size_t)idx * 16);
            }
            CPA_COMMIT();
        }

        float acc[2][4][4];
#pragma unroll
        for (int mt = 0; mt < 2; mt++)
#pragma unroll
            for (int nt = 0; nt < 4; nt++)
#pragma unroll
                for (int q2 = 0; q2 < 4; q2++) acc[mt][nt][q2] = 0.f;

        uint32_t obh = OFF_B(j & 1, 0), obl = OFF_B(j & 1, 1);
#pragma unroll
        for (int ks = 0; ks < 8; ks++) {
            uint32_t ah[2][4], al[2][4];
#pragma unroll
            for (int mt = 0; mt < 2; mt++) {
                uint32_t off = ((a_row + mt * 16) * SA + ks * 16 + a_coff) * 2;
                ldmat4(ah[mt][0], ah[mt][1], ah[mt][2], ah[mt][3], sb + OFF_A_HI + off);
                ldmat4(al[mt][0], al[mt][1], al[mt][2], al[mt][3], sb + OFF_A_LO + off);
            }
            uint32_t bh[4][2], bl[4][2];
#pragma unroll
            for (int np = 0; np < 2; np++) {
                uint32_t off = ((b_row + np * 16) * SA + ks * 16 + b_coff) * 2;
                ldmat4(bh[2 * np][0], bh[2 * np][1], bh[2 * np + 1][0], bh[2 * np + 1][1],
                       sb + obh + off);
                ldmat4(bl[2 * np][0], bl[2 * np][1], bl[2 * np + 1][0], bl[2 * np + 1][1],
                       sb + obl + off);
            }
#pragma unroll
            for (int mt = 0; mt < 2; mt++)
#pragma unroll
                for (int nt = 0; nt < 4; nt++) {
                    mma16816(acc[mt][nt], ah[mt], bh[nt]);
                    mma16816(acc[mt][nt], ah[mt], bl[nt]);
                    mma16816(acc[mt][nt], al[mt], bh[nt]);
                }
        }

        // ---- epilogue (register-only) ----
        {
            const float* bs = p.bias[j];
            float* outp = p.out[j];
            int oc = p.oc[j], ldc = p.ldc[j], act = p.act[j], sdv = p.sdinv[j];
#pragma unroll
            for (int mt = 0; mt < 2; mt++) {
                int r0 = row0 + wm * 32 + mt * 16 + (lane >> 2);
                int r1 = r0 + 8;
                float sc0 = 1.f, sc1 = 1.f;
                if (sdv) {
                    if (r0 < p.nrows) sc0 = g_dinv[r0];
                    if (r1 < p.nrows) sc1 = g_dinv[r1];
                }
#pragma unroll
                for (int nt = 0; nt < 4; nt++) {
                    int c = wn * 32 + nt * 8 + (lane & 3) * 2;
                    if (c >= oc) continue;
                    float b0 = bs ? bs[c] : 0.f;
                    float b1 = bs ? bs[c + 1] : 0.f;
                    float d0 = acc[mt][nt][0] + b0;
                    float d1 = acc[mt][nt][1] + b1;
                    float d2 = acc[mt][nt][2] + b0;
                    float d3 = acc[mt][nt][3] + b1;
                    if (act == ACT_RELU) {
                        d0 = fmaxf(d0, 0.f); d1 = fmaxf(d1, 0.f);
                        d2 = fmaxf(d2, 0.f); d3 = fmaxf(d3, 0.f);
                    } else if (act == ACT_SIGM) {
                        d0 = 1.f / (1.f + expf(-d0));
                        d1 = 1.f / (1.f + expf(-d1));
                        d2 = 1.f / (1.f + expf(-d2));
                        d3 = 1.f / (1.f + expf(-d3));
                    }
                    d0 *= sc0; d1 *= sc0; d2 *= sc1; d3 *= sc1;
                    if (r0 < p.nrows) *(float2*)(outp + (size_t)r0 * ldc + c) = make_float2(d0, d1);
                    if (r1 < p.nrows) *(float2*)(outp + (size_t)r1 * ldc + c) = make_float2(d2, d3);
                }
            }
        }

        if (j + 1 < p.nout) {
            CPA_WAIT0();
            __syncthreads();
        }
    }
}

// ------------------- edge dtype detect + CSR build -------------------
__global__ void detect_k(const int* __restrict__ w, int nwords)
{
    __shared__ int any;
    if (threadIdx.x == 0) any = 0;
    __syncthreads();
    int npairs = min(nwords >> 1, 2048);
    for (int i = threadIdx.x; i < npairs; i += blockDim.x)
        if (w[2 * i + 1] != 0) atomicOr(&any, 1);
    __syncthreads();
    if (threadIdx.x == 0) g_is64 = (any == 0) ? 1 : 0;
}

__device__ __forceinline__ int edge_at(const void* ei, long long idx)
{
    return g_is64 ? (int)((const long long*)ei)[idx] : ((const int*)ei)[idx];
}

__global__ void hist_k(const void* __restrict__ ei, long long eoff, int ne)
{
    for (int e = blockIdx.x * blockDim.x + threadIdx.x; e < ne; e += gridDim.x * blockDim.x)
        atomicAdd(&g_deg[edge_at(ei, eoff + e)], 1);
}

__global__ void scan1(int n)
{
    __shared__ int wsum[32];
    int t = threadIdx.x;
    int idx = blockIdx.x * 4096 + t * 4;
    int v0 = (idx + 0 < n) ? g_deg[idx + 0] : 0;
    int v1 = (idx + 1 < n) ? g_deg[idx + 1] : 0;
    int v2 = (idx + 2 < n) ? g_deg[idx + 2] : 0;
    int v3 = (idx + 3 < n) ? g_deg[idx + 3] : 0;
    if (idx + 0 < n) g_dinv[idx + 0] = rsqrtf((float)(v0 + 1));
    if (idx + 1 < n) g_dinv[idx + 1] = rsqrtf((float)(v1 + 1));
    if (idx + 2 < n) g_dinv[idx + 2] = rsqrtf((float)(v2 + 1));
    if (idx + 3 < n) g_dinv[idx + 3] = rsqrtf((float)(v3 + 1));
    int tsum = v0 + v1 + v2 + v3;
    int lane = t & 31, w = t >> 5;
    int inc = tsum;
#pragma unroll
    for (int o = 1; o < 32; o <<= 1) {
        int y = __shfl_up_sync(0xffffffffu, inc, o);
        if (lane >= o) inc += y;
    }
    if (lane == 31) wsum[w] = inc;
    __syncthreads();
    if (w == 0) {
        int y = wsum[lane];
#pragma unroll
        for (int o = 1; o < 32; o <<= 1) {
            int z = __shfl_up_sync(0xffffffffu, y, o);
            if (lane >= o) y += z;
        }
        wsum[lane] = y;
    }
    __syncthreads();
    int excl = inc - tsum + (w > 0 ? wsum[w - 1] : 0);
    if (idx + 0 < n) g_rowp[idx + 0] = excl;
    if (idx + 1 < n) g_rowp[idx + 1] = excl + v0;
    if (idx + 2 < n) g_rowp[idx + 2] = excl + v0 + v1;
    if (idx + 3 < n) g_rowp[idx + 3] = excl + v0 + v1 + v2;
    if (t == 0) g_bsum[blockIdx.x] = wsum[31];
}

__global__ void scan2(int nb)
{
    if (threadIdx.x == 0 && blockIdx.x == 0) {
        int s = 0;
        for (int i = 0; i < nb; i++) { int t = g_bsum[i]; g_bsum[i] = s; s += t; }
    }
}

__global__ void scan3(int n, int total)
{
    int t = threadIdx.x;
    int idx = blockIdx.x * 4096 + t * 4;
    int off = g_bsum[blockIdx.x];
#pragma unroll
    for (int j = 0; j < 4; j++)
        if (idx + j < n) g_rowp[idx + j] += off;
    if (blockIdx.x == 0 && t == 0) g_rowp[n] = total;
}

__global__ void scatter_k(const void* __restrict__ ei, long long eoff, int ne)
{
    for (int e = blockIdx.x * blockDim.x + threadIdx.x; e < ne; e += gridDim.x * blockDim.x) {
        int d = edge_at(ei, eoff + e);
        int s = edge_at(ei, e);
        int pos = g_rowp[d] + atomicAdd(&g_fill[d], 1);
        g_col[pos] = s;
    }
}

// ------------------- kv = k^T v  (fp32, atomic finalize) + fused ksum -----------
__global__ __launch_bounds__(256)
void kv_k(const float* __restrict__ kk, const float* __restrict__ vv, int n)
{
    __shared__ float ks[32][128];
    __shared__ float vs[32][128];
    int t = threadIdx.x;
    int tx = t & 15, ty = t >> 4;
    int base = blockIdx.x * 512;
    int end = min(base + 512, n);

    int kcol = t & 127, krh = (t >> 7) * 16;
    float ksacc = 0.f;

    ull acc[4][8];
#pragma unroll
    for (int i = 0; i < 4; i++)
#pragma unroll
        for (int j = 0; j < 8; j++) acc[i][j] = 0ULL;

    for (int nb = base; nb < end; nb += 32) {
#pragma unroll
        for (int q = 0; q < 4; q++) {
            int idx = t + 256 * q;
            int r = idx >> 5, c = (idx & 31) * 4;
            int gr = nb + r;
            float4 a = make_float4(0, 0, 0, 0), b = make_float4(0, 0, 0, 0);
            if (gr < n) {
                a = *(const float4*)(kk + (size_t)gr * 128 + c);
                b = *(const float4*)(vv + (size_t)gr * 128 + c);
            }
            *(float4*)&ks[r][c] = a;
            *(float4*)&vs[r][c] = b;
        }
        __syncthreads();
#pragma unroll
        for (int r = 0; r < 16; r++) ksacc += ks[krh + r][kcol];
#pragma unroll 8
        for (int nn = 0; nn < 32; nn++) {
            ull a2[4];
            a2[0] = *(const ull*)&ks[nn][ty * 8 + 0];
            a2[1] = *(const ull*)&ks[nn][ty * 8 + 2];
            a2[2] = *(const ull*)&ks[nn][ty * 8 + 4];
            a2[3] = *(const ull*)&ks[nn][ty * 8 + 6];
            float b[8];
            *(float4*)&b[0] = *(const float4*)&vs[nn][tx * 8];
            *(float4*)&b[4] = *(const float4*)&vs[nn][tx * 8 + 4];
#pragma unroll
            for (int j = 0; j < 8; j++) {
                ull bd = pk2(b[j]);
#pragma unroll
                for (int i = 0; i < 4; i++) acc[i][j] = fma2(a2[i], bd, acc[i][j]);
            }
        }
        __syncthreads();
    }
#pragma unroll
    for (int i = 0; i < 4; i++)
#pragma unroll
        for (int j = 0; j < 8; j++) {
            float lo, hi;
            upk(acc[i][j], lo, hi);
            int d = ty * 8 + 2 * i, m = tx * 8 + j;
            atomicAdd(&g_kvs[d * 128 + m], lo);
            atomicAdd(&g_kvs[(d + 1) * 128 + m], hi);
        }
    ((float*)ks)[t] = ksacc;
    __syncthreads();
    if (t < 128) atomicAdd(&g_kvs[16384 + t], ksacc + ((float*)ks)[t + 128]);
}

// ------------------- fused SpMM + GCN-layer epilogue (warp per node) ------------
// g_xw holds y = xw * dinv (pre-scaled in GEMM epilogue)
__global__ __launch_bounds__(256)
void spmm_epi(const float* __restrict__ bg,
              const float* __restrict__ bng, const float* __restrict__ bnb,
              const float* __restrict__ bnrm, const float* __restrict__ bnrv,
              const float* __restrict__ lng, const float* __restrict__ lnb,
              int n, int first, int last)
{
    int w = (blockIdx.x * blockDim.x + threadIdx.x) >> 5;
    int lane = threadIdx.x & 31;
    if (w >= n) return;
    int c0 = lane * 4;

    float4 acc = *(const float4*)(g_xw + (size_t)w * 128 + c0);   // self term y_w
    int e0 = g_rowp[w], e1 = g_rowp[w + 1];
    if (e0 < e1) {
        // 2-deep pipeline: prefetch next column index AND next value row
        int c_next = g_col[e0];
        float4 v_next = *(const float4*)(g_xw + (size_t)c_next * 128 + c0);
        for (int e = e0; e < e1; e++) {
            float4 v = v_next;
            if (e + 1 < e1) {
                int cn = g_col[e + 1];
                v_next = *(const float4*)(g_xw + (size_t)cn * 128 + c0);
            }
            acc.x += v.x; acc.y += v.y; acc.z += v.z; acc.w += v.w;
        }
    }
    float di = g_dinv[w];
    float4 lv = *(const float4*)(g_lin + (size_t)w * 128 + c0);
    float4 xv;
    xv.x = acc.x * di + bg[c0 + 0] + lv.x;
    xv.y = acc.y * di + bg[c0 + 1] + lv.y;
    xv.z = acc.z * di + bg[c0 + 2] + lv.z;
    xv.w = acc.w * di + bg[c0 + 3] + lv.w;
#pragma unroll
    for (int j = 0; j < 4; j++) {
        float s = bng[c0 + j] * rsqrtf(bnrv[c0 + j] + 1e-5f);
        float* p = &xv.x + j;
        *p = fmaxf((*p - bnrm[c0 + j]) * s + bnb[c0 + j], 0.f);
    }
    float4 hv = *(const float4*)(g_h + (size_t)w * 128 + c0);
    float4 tv;
    tv.x = hv.x * xv.x; tv.y = hv.y * xv.y; tv.z = hv.z * xv.z; tv.w = hv.w * xv.w;
    float s1 = tv.x + tv.y + tv.z + tv.w;
    float s2 = tv.x * tv.x + tv.y * tv.y + tv.z * tv.z + tv.w * tv.w;
    s1 = wsumf(s1); s2 = wsumf(s2);
    float mu = s1 * (1.f / 128.f);
    float var = s2 * (1.f / 128.f) - mu * mu;
    float rs = rsqrtf(var + 1e-5f);
#pragma unroll
    for (int j = 0; j < 4; j++) {
        float* pt = &tv.x + j;
        float* px = &xv.x + j;
        float y = (*pt - mu) * rs * lng[c0 + j] + lnb[c0 + j];
        *px = 0.1f * y + 0.9f * (*px);
    }
    float4 xl = make_float4(0, 0, 0, 0);
    if (!first) xl = *(const float4*)(g_xloc + (size_t)w * 128 + c0);
    xl.x += xv.x; xl.y += xv.y; xl.z += xv.z; xl.w += xv.w;
    *(float4*)(g_xloc + (size_t)w * 128 + c0) = xl;
    if (!last) *(float4*)(g_x + (size_t)w * 128 + c0) = xv;
}

// ------------------- host orchestration -------------------
static inline void fill1(TCParams& p, int i, const __nv_bfloat16* bh, const __nv_bfloat16* bl,
                         const float* bias, float* out, int oc, int ldc, int act, int sdv = 0)
{
    p.bhi[i] = bh; p.blo[i] = bl; p.bias[i] = bias; p.out[i] = out;
    p.oc[i] = oc; p.ldc[i] = ldc; p.act[i] = act; p.sdinv[i] = sdv;
}

extern "C" void kernel_launch(void* const* d_in, const int* in_sizes, int n_in,
                              void* d_out, int out_size)
{
    const float* in_x  = (const float*)d_in[0];
    const void*  ei    = d_in[1];
    const float* Wh    = (const float*)d_in[2];
    const float* bh    = (const float*)d_in[3];
    const float* Wg    = (const float*)d_in[4];
    const float* bg    = (const float*)d_in[5];
    const float* Wl    = (const float*)d_in[6];
    const float* bl    = (const float*)d_in[7];
    const float* ln_g  = (const float*)d_in[8];
    const float* ln_b  = (const float*)d_in[9];
    const float* bn_g  = (const float*)d_in[10];
    const float* bn_b  = (const float*)d_in[11];
    const float* bn_rm = (const float*)d_in[12];
    const float* bn_rv = (const float*)d_in[13];
    const float* gWh   = (const float*)d_in[14];
    const float* gbh   = (const float*)d_in[15];
    const float* gWk   = (const float*)d_in[16];
    const float* gWv   = (const float*)d_in[17];
    const float* gln_g = (const float*)d_in[18];
    const float* gln_b = (const float*)d_in[19];
    const float* gWo   = (const float*)d_in[20];
    const float* gbo   = (const float*)d_in[21];
    const float* f_ln_g = (const float*)d_in[22];
    const float* f_ln_b = (const float*)d_in[23];
    const float* Wp    = (const float*)d_in[24];
    const float* bp    = (const float*)d_in[25];

    int n  = in_sizes[0] / 128;
    int ne = in_sizes[1] / 2;

    float *px, *ph, *pxw, *plin, *pxloc, *pxg, *pk, *pkvs;
    __nv_bfloat16 *pBhi, *pBlo;
    int *pdeg, *pfill;
    cudaGetSymbolAddress((void**)&px, g_x);
    cudaGetSymbolAddress((void**)&ph, g_h);
    cudaGetSymbolAddress((void**)&pxw, g_xw);
    cudaGetSymbolAddress((void**)&plin, g_lin);
    cudaGetSymbolAddress((void**)&pxloc, g_xloc);
    cudaGetSymbolAddress((void**)&pxg, g_xg);
    cudaGetSymbolAddress((void**)&pk, g_k);
    cudaGetSymbolAddress((void**)&pkvs, g_kvs);
    cudaGetSymbolAddress((void**)&pdeg, g_deg);
    cudaGetSymbolAddress((void**)&pfill, g_fill);
    cudaGetSymbolAddress((void**)&pBhi, g_Bhi);
    cudaGetSymbolAddress((void**)&pBlo, g_Blo);

    cudaFuncSetAttribute(gemm_tc, cudaFuncAttributeMaxDynamicSharedMemorySize, SMEM_TOTAL);

    int gg = (n + 127) / 128;
    int wg = (n * 32 + 255) / 256;
    int nblk = (n + 4095) / 4096;

    cudaMemsetAsync(pdeg, 0, (size_t)n * 4);
    cudaMemsetAsync(pfill, 0, (size_t)n * 4);

    prep_all<<<(30 * 16384 + 255) / 256, 256>>>(Wh, Wg, Wl, gWh, gWk, gWv, gWo, Wp, pBhi, pBlo);
    detect_k<<<1, 256>>>((const int*)ei, ne * 2);
    hist_k<<<2048, 256>>>(ei, (long long)ne, ne);
    scan1<<<nblk, 1024>>>(n);
    scan2<<<1, 32>>>(nblk);

    // first GEMM (layer 1) — A = in_x
    {
        TCParams p = {};
        p.A = in_x; p.nrows = n; p.nout = 3; p.amode = AM_PLAIN;
        fill1(p, 0, pBhi + (size_t)0 * 16384,  pBlo + (size_t)0 * 16384,  bh, ph,   128, 128, ACT_RELU);
        fill1(p, 1, pBhi + (size_t)7 * 16384,  pBlo + (size_t)7 * 16384,  nullptr, pxw,  128, 128, ACT_NONE, 1);
        fill1(p, 2, pBhi + (size_t)14 * 16384, pBlo + (size_t)14 * 16384, bl, plin, 128, 128, ACT_NONE);
        gemm_tc<<<gg, 512, SMEM_TOTAL>>>(p);
    }

    scan3<<<nblk, 1024>>>(n, ne);
    scatter_k<<<2048, 256>>>(ei, (long long)ne, ne);

    spmm_epi<<<wg, 256>>>(bg, bn_g, bn_b, bn_rm, bn_rv, ln_g, ln_b, n, 1, 0);

    for (int i = 1; i < 7; i++) {
        TCParams p = {};
        p.A = px; p.nrows = n; p.nout = 3; p.amode = AM_PLAIN;
        fill1(p, 0, pBhi + (size_t)i * 16384,        pBlo + (size_t)i * 16384,        bh + i * 128, ph,   128, 128, ACT_RELU);
        fill1(p, 1, pBhi + (size_t)(7 + i) * 16384,  pBlo + (size_t)(7 + i) * 16384,  nullptr,      pxw,  128, 128, ACT_NONE, 1);
        fill1(p, 2, pBhi + (size_t)(14 + i) * 16384, pBlo + (size_t)(14 + i) * 16384, bl + i * 128, plin, 128, 128, ACT_NONE);
        gemm_tc<<<gg, 512, SMEM_TOTAL>>>(p);
        spmm_epi<<<wg, 256>>>(bg + i * 128, bn_g + i * 128, bn_b + i * 128,
                              bn_rm + i * 128, bn_rv + i * 128,
                              ln_g + i * 128, ln_b + i * 128, n, 0, i == 6);
    }

    // global attention (LN fused into first projection GEMM; attn_epi fused into out-GEMM)
    for (int j = 0; j < 2; j++) {
        {
            TCParams p = {};
            p.nrows = n; p.nout = 3;
            if (j == 0) { p.A = pxloc; p.amode = AM_LN; p.lng = f_ln_g; p.lnb = f_ln_b; }
            else        { p.A = pxg;   p.amode = AM_PLAIN; }
            fill1(p, 0, pBhi + (size_t)(21 + j) * 16384, pBlo + (size_t)(21 + j) * 16384, gbh + j * 128, ph,  128, 128, ACT_NONE);
            fill1(p, 1, pBhi + (size_t)(23 + j) * 16384, pBlo + (size_t)(23 + j) * 16384, nullptr,       pk,  128, 128, ACT_SIGM);
            fill1(p, 2, pBhi + (size_t)(25 + j) * 16384, pBlo + (size_t)(25 + j) * 16384, nullptr,       pxw, 128, 128, ACT_NONE);
            gemm_tc<<<gg, 512, SMEM_TOTAL>>>(p);
        }
        cudaMemsetAsync(pkvs, 0, (128 * 128 + 128) * 4);
        kv_k<<<(n + 511) / 512, 256>>>(pk, pxw, n);
        prep_kv<<<(16384 + 255) / 256, 256>>>(pBhi, pBlo);
        {
            TCParams p = {};
            p.A = pk; p.nrows = n; p.nout = 1; p.amode = AM_PLAIN;
            fill1(p, 0, pBhi + (size_t)30 * 16384, pBlo + (size_t)30 * 16384, nullptr, plin, 128, 128, ACT_NONE);
            gemm_tc<<<gg, 512, SMEM_TOTAL>>>(p);
        }
        {
            // out-GEMM with fused attention epilogue as A-transform
            TCParams p = {};
            p.A = plin; p.nrows = n; p.nout = 1; p.amode = AM_ATTN;
            p.lng = gln_g + j * 128; p.lnb = gln_b + j * 128;
            p.q = pk; p.hg = ph;
            fill1(p, 0, pBhi + (size_t)(27 + j) * 16384, pBlo + (size_t)(27 + j) * 16384, gbo + j * 128, pxg, 128, 128, ACT_RELU);
            gemm_tc<<<gg, 512, SMEM_TOTAL>>>(p);
        }
    }

    // final projection (oc=40)
    {
        TCParams p = {};
        p.A = pxg; p.nrows = n; p.nout = 1; p.amode = AM_PLAIN;
        fill1(p, 0, pBhi + (size_t)29 * 16384, pBlo + (size_t)29 * 16384, bp, (float*)d_out, 40, 40, ACT_NONE);
        gemm_tc<<<gg, 512, SMEM_TOTAL>>>(p);
    }
}

// round 15
// speedup vs baseline: 1.5346x; 1.0296x over previous
#include <cuda_runtime.h>
#include <cuda_bf16.h>
#include <cstddef>
#include <cstdint>

#define NMAX 100000
#define EMAX 1600000
#define CH 128

typedef unsigned long long ull;

// ------------------- device scratch (no allocations allowed) -------------------
__device__ __align__(16) float g_x   [NMAX * CH];
__device__ __align__(16) float g_h   [NMAX * CH];
__device__ __align__(16) float g_xw  [NMAX * CH];   // GCN: y = xw*dinv ; attn: v
__device__ __align__(16) float g_lin [NMAX * CH];   // also num
__device__ __align__(16) float g_xloc[NMAX * CH];
__device__ __align__(16) float g_xg  [NMAX * CH];
__device__ __align__(16) float g_k   [NMAX * CH];
__device__ __align__(16) float g_dinv[NMAX];
__device__ int   g_deg [NMAX];
__device__ int   g_rowp[NMAX + 1];
__device__ int   g_fill[NMAX];
__device__ int   g_col [EMAX];
__device__ int   g_bsum[64];
__device__ int   g_is64;
// kv [128][128] followed by ksum[128]
__device__ __align__(16) float g_kvs [CH * CH + CH];
// pre-split bf16 weights, row-major [n=128][k=128] per slot (slot 30 = kv)
__device__ __align__(16) __nv_bfloat16 g_Bhi[31 * 16384];
__device__ __align__(16) __nv_bfloat16 g_Blo[31 * 16384];

// ------------------- f32x2 helpers (kv kernel) -------------------
__device__ __forceinline__ ull fma2(ull a, ull b, ull c) {
    ull d; asm("fma.rn.f32x2 %0, %1, %2, %3;" : "=l"(d) : "l"(a), "l"(b), "l"(c));
    return d;
}
__device__ __forceinline__ ull pk2(float v) {
    ull r; asm("mov.b64 %0, {%1, %1};" : "=l"(r) : "f"(v)); return r;
}
__device__ __forceinline__ void upk(ull v, float& lo, float& hi) {
    asm("mov.b64 {%0, %1}, %2;" : "=f"(lo), "=f"(hi) : "l"(v));
}
__device__ __forceinline__ float wsumf(float v) {
#pragma unroll
    for (int o = 16; o; o >>= 1) v += __shfl_xor_sync(0xffffffffu, v, o);
    return v;
}

// streaming (evict-first) load/store of float4
__device__ __forceinline__ float4 ldcs4(const float* p) {
    float4 v;
    asm volatile("ld.global.cs.v4.f32 {%0,%1,%2,%3}, [%4];"
                 : "=f"(v.x), "=f"(v.y), "=f"(v.z), "=f"(v.w) : "l"(p));
    return v;
}
__device__ __forceinline__ void stcs4(float* p, float4 v) {
    asm volatile("st.global.cs.v4.f32 [%0], {%1,%2,%3,%4};"
                 :: "l"(p), "f"(v.x), "f"(v.y), "f"(v.z), "f"(v.w));
}

// ------------------- mma / cp.async helpers -------------------
__device__ __forceinline__ uint32_t smem_u32(const void* p) {
    uint32_t a;
    asm("{ .reg .u64 t; cvta.to.shared.u64 t, %1; cvt.u32.u64 %0, t; }" : "=r"(a) : "l"(p));
    return a;
}
__device__ __forceinline__ void ldmat4(uint32_t& r0, uint32_t& r1, uint32_t& r2, uint32_t& r3,
                                       uint32_t addr) {
    asm volatile("ldmatrix.sync.aligned.m8n8.x4.shared.b16 {%0,%1,%2,%3}, [%4];"
                 : "=r"(r0), "=r"(r1), "=r"(r2), "=r"(r3) : "r"(addr));
}
__device__ __forceinline__ void mma16816(float* d, const uint32_t* a, const uint32_t* b) {
    asm volatile(
        "mma.sync.aligned.m16n8k16.row.col.f32.bf16.bf16.f32 "
        "{%0,%1,%2,%3}, {%4,%5,%6,%7}, {%8,%9}, {%0,%1,%2,%3};"
        : "+f"(d[0]), "+f"(d[1]), "+f"(d[2]), "+f"(d[3])
        : "r"(a[0]), "r"(a[1]), "r"(a[2]), "r"(a[3]), "r"(b[0]), "r"(b[1]));
}
__device__ __forceinline__ void cpa16(uint32_t dst, const void* src) {
    asm volatile("cp.async.cg.shared.global [%0], [%1], 16;" :: "r"(dst), "l"(src));
}
#define CPA_COMMIT() asm volatile("cp.async.commit_group;" ::: "memory")
#define CPA_WAIT0()  asm volatile("cp.async.wait_group 0;" ::: "memory")

__device__ __forceinline__ void splitpack(float a, float b, uint32_t& hw, uint32_t& lw) {
    __nv_bfloat16 ha = __float2bfloat16(a), hb = __float2bfloat16(b);
    float ra = a - __bfloat162float(ha), rb = b - __bfloat162float(hb);
    __nv_bfloat16 la = __float2bfloat16(ra), lb = __float2bfloat16(rb);
    __nv_bfloat162 hv(ha, hb), lv(la, lb);
    hw = *(uint32_t*)&hv; lw = *(uint32_t*)&lv;
}

// ------------------- weight prep -------------------
__global__ void prep_all(const float* __restrict__ Wh, const float* __restrict__ Wg,
                         const float* __restrict__ Wl, const float* __restrict__ gWh,
                         const float* __restrict__ gWk, const float* __restrict__ gWv,
                         const float* __restrict__ gWo, const float* __restrict__ Wp,
                         __nv_bfloat16* __restrict__ dhi, __nv_bfloat16* __restrict__ dlo)
{
    int idx = blockIdx.x * blockDim.x + threadIdx.x;
    if (idx >= 30 * 16384) return;
    int s = idx >> 14;
    const float* src; int m; int oc = 128;
    if      (s < 7)  { src = Wh;  m = s; }
    else if (s < 14) { src = Wg;  m = s - 7; }
    else if (s < 21) { src = Wl;  m = s - 14; }
    else if (s < 23) { src = gWh; m = s - 21; }
    else if (s < 25) { src = gWk; m = s - 23; }
    else if (s < 27) { src = gWv; m = s - 25; }
    else if (s < 29) { src = gWo; m = s - 27; }
    else             { src = Wp;  m = 0; oc = 40; }
    int rem = idx & 16383, o = rem >> 7, k = rem & 127;
    float v = (o < oc) ? src[(size_t)m * oc * 128 + (size_t)o * 128 + k] : 0.f;
    __nv_bfloat16 hi = __float2bfloat16(v);
    dhi[idx] = hi;
    dlo[idx] = __float2bfloat16(v - __bfloat162float(hi));
}

__global__ void prep_kv(__nv_bfloat16* __restrict__ dhi, __nv_bfloat16* __restrict__ dlo)
{
    int idx = blockIdx.x * blockDim.x + threadIdx.x;
    if (idx >= 16384) return;
    int o = idx >> 7, k = idx & 127;
    float v = g_kvs[k * 128 + o];
    __nv_bfloat16 hi = __float2bfloat16(v);
    dhi[(size_t)30 * 16384 + idx] = hi;
    dlo[(size_t)30 * 16384 + idx] = __float2bfloat16(v - __bfloat162float(hi));
}

// ------------------- tensor-core GEMM: up to 3 products sharing A -------------------
#define ACT_NONE 0
#define ACT_RELU 1
#define ACT_SIGM 2

#define AM_PLAIN 0
#define AM_LN    1
#define AM_ATTN  2

struct TCParams {
    const float* A; int nrows; int nout; int amode;
    const float* lng; const float* lnb;          // LN / ATTN params
    const float* q; const float* hg;             // ATTN: q rows, gate rows
    const __nv_bfloat16* bhi[3]; const __nv_bfloat16* blo[3];
    const float* bias[3]; float* out[3];
    int oc[3]; int ldc[3]; int act[3]; int sdinv[3];
};

#define SA 136                       // smem row stride in bf16 elems (272B)
#define SM_TILE (128 * SA * 2)       // 34816 bytes per tile image
#define OFF_A_HI 0
#define OFF_A_LO SM_TILE
#define OFF_B(buf, img) ((uint32_t)(2 + (buf) * 2 + (img)) * SM_TILE)
#define SMEM_TOTAL (6 * SM_TILE)     // 208896 bytes

__global__ __launch_bounds__(512, 1) void gemm_tc(TCParams p)
{
    extern __shared__ __align__(16) char smem[];
    uint32_t sb = smem_u32(smem);
    int t = threadIdx.x;
    int lane = t & 31, wid = t >> 5;
    int wm = wid >> 2, wn = wid & 3;       // warp grid 4x4 -> warp tile 32x32
    int row0 = blockIdx.x * 128;

    // ---- prefetch B0 via cp.async (overlaps A conversion) ----
    {
        const char* sh = (const char*)p.bhi[0];
        const char* sl = (const char*)p.blo[0];
#pragma unroll
        for (int i = 0; i < 4; i++) {
            int idx = i * 512 + t;               // 2048 chunks of 16B per image
            int r = idx >> 4, c8 = (idx & 15) * 8;
            uint32_t boff = (uint32_t)r * (SA * 2) + c8 * 2;
            cpa16(sb + OFF_B(0, 0) + boff, sh + (size_t)idx * 16);
            cpa16(sb + OFF_B(0, 1) + boff, sl + (size_t)idx * 16);
        }
        CPA_COMMIT();
    }

    // ---- A load (+ optional fused row transform) + split to bf16 hi/lo ----
    // each warp owns whole rows: iteration i covers row r = i*16 + wid
#pragma unroll
    for (int i = 0; i < 8; i++) {
        int r = i * 16 + wid;
        int gr = row0 + r;
        int c0 = lane * 4;
        float4 v = make_float4(0.f, 0.f, 0.f, 0.f);
        if (gr < p.nrows) v = *(const float4*)(p.A + (size_t)gr * 128 + c0);

        if (p.amode == AM_LN) {
            float s1 = v.x + v.y + v.z + v.w;
            float s2 = v.x * v.x + v.y * v.y + v.z * v.z + v.w * v.w;
            s1 = wsumf(s1); s2 = wsumf(s2);
            float mu = s1 * (1.f / 128.f);
            float var = s2 * (1.f / 128.f) - mu * mu;
            float rs = rsqrtf(var + 1e-5f);
            v.x = (v.x - mu) * rs * p.lng[c0 + 0] + p.lnb[c0 + 0];
            v.y = (v.y - mu) * rs * p.lng[c0 + 1] + p.lnb[c0 + 1];
            v.z = (v.z - mu) * rs * p.lng[c0 + 2] + p.lnb[c0 + 2];
            v.w = (v.w - mu) * rs * p.lng[c0 + 3] + p.lnb[c0 + 3];
        } else if (p.amode == AM_ATTN) {
            float4 qv = make_float4(0, 0, 0, 0), hv = qv;
            if (gr < p.nrows) {
                qv = *(const float4*)(p.q  + (size_t)gr * 128 + c0);
                hv = *(const float4*)(p.hg + (size_t)gr * 128 + c0);
            }
            float4 ksv = *(const float4*)(g_kvs + 16384 + c0);
            float den = qv.x * ksv.x + qv.y * ksv.y + qv.z * ksv.z + qv.w * ksv.w;
            den = wsumf(den);
            float inv = 1.f / (den + 1e-6f);
            v.x *= inv; v.y *= inv; v.z *= inv; v.w *= inv;
            float s1 = v.x + v.y + v.z + v.w;
            float s2 = v.x * v.x + v.y * v.y + v.z * v.z + v.w * v.w;
            s1 = wsumf(s1); s2 = wsumf(s2);
            float mu = s1 * (1.f / 128.f);
            float var = s2 * (1.f / 128.f) - mu * mu;
            float rs = rsqrtf(var + 1e-5f);
            v.x = ((v.x - mu) * rs * p.lng[c0 + 0] + p.lnb[c0 + 0]) * (hv.x + 0.9f);
            v.y = ((v.y - mu) * rs * p.lng[c0 + 1] + p.lnb[c0 + 1]) * (hv.y + 0.9f);
            v.z = ((v.z - mu) * rs * p.lng[c0 + 2] + p.lnb[c0 + 2]) * (hv.z + 0.9f);
            v.w = ((v.w - mu) * rs * p.lng[c0 + 3] + p.lnb[c0 + 3]) * (hv.w + 0.9f);
        }

        uint32_t h0, h1, l0, l1;
        splitpack(v.x, v.y, h0, l0);
        splitpack(v.z, v.w, h1, l1);
        uint32_t boff = (uint32_t)r * (SA * 2) + (uint32_t)c0 * 2;
        *(uint2*)(smem + OFF_A_HI + boff) = make_uint2(h0, h1);
        *(uint2*)(smem + OFF_A_LO + boff) = make_uint2(l0, l1);
    }
    CPA_WAIT0();
    __syncthreads();

    int g = lane >> 3, l7 = lane & 7;
    uint32_t a_row  = (uint32_t)(wm * 32 + (g & 1) * 8 + l7);
    uint32_t a_coff = (uint32_t)((g >> 1) * 8);
    uint32_t b_row  = (uint32_t)(wn * 32 + (g >> 1) * 8 + l7);
    uint32_t b_coff = (uint32_t)((g & 1) * 8);

    for (int j = 0; j < p.nout; j++) {
        if (j + 1 < p.nout) {
            const char* sh = (const char*)p.bhi[j + 1];
            const char* sl = (const char*)p.blo[j + 1];
            uint32_t bufh = OFF_B((j + 1) & 1, 0), bufl = OFF_B((j + 1) & 1, 1);
#pragma unroll
            for (int i = 0; i < 4; i++) {
                int idx = i * 512 + t;
                int r = idx >> 4, c8 = (idx & 15) * 8;
                uint32_t boff = (uint32_t)r * (SA * 2) + c8 * 2;
                cpa16(sb + bufh + boff, sh + (size_t)idx * 16);
                cpa16(sb + bufl + boff, sl + (size_t)idx * 16);
            }
            CPA_COMMIT();
        }

        float acc[2][4][4];
#pragma unroll
        for (int mt = 0; mt < 2; mt++)
#pragma unroll
            for (int nt = 0; nt < 4; nt++)
#pragma unroll
                for (int q2 = 0; q2 < 4; q2++) acc[mt][nt][q2] = 0.f;

        uint32_t obh = OFF_B(j & 1, 0), obl = OFF_B(j & 1, 1);
#pragma unroll
        for (int ks = 0; ks < 8; ks++) {
            uint32_t ah[2][4], al[2][4];
#pragma unroll
            for (int mt = 0; mt < 2; mt++) {
                uint32_t off = ((a_row + mt * 16) * SA + ks * 16 + a_coff) * 2;
                ldmat4(ah[mt][0], ah[mt][1], ah[mt][2], ah[mt][3], sb + OFF_A_HI + off);
                ldmat4(al[mt][0], al[mt][1], al[mt][2], al[mt][3], sb + OFF_A_LO + off);
            }
            uint32_t bh[4][2], bl[4][2];
#pragma unroll
            for (int np = 0; np < 2; np++) {
                uint32_t off = ((b_row + np * 16) * SA + ks * 16 + b_coff) * 2;
                ldmat4(bh[2 * np][0], bh[2 * np][1], bh[2 * np + 1][0], bh[2 * np + 1][1],
                       sb + obh + off);
                ldmat4(bl[2 * np][0], bl[2 * np][1], bl[2 * np + 1][0], bl[2 * np + 1][1],
                       sb + obl + off);
            }
#pragma unroll
            for (int mt = 0; mt < 2; mt++)
#pragma unroll
                for (int nt = 0; nt < 4; nt++) {
                    mma16816(acc[mt][nt], ah[mt], bh[nt]);
                    mma16816(acc[mt][nt], ah[mt], bl[nt]);
                    mma16816(acc[mt][nt], al[mt], bh[nt]);
                }
        }

        // ---- epilogue (register-only) ----
        {
            const float* bs = p.bias[j];
            float* outp = p.out[j];
            int oc = p.oc[j], ldc = p.ldc[j], act = p.act[j], sdv = p.sdinv[j];
#pragma unroll
            for (int mt = 0; mt < 2; mt++) {
                int r0 = row0 + wm * 32 + mt * 16 + (lane >> 2);
                int r1 = r0 + 8;
                float sc0 = 1.f, sc1 = 1.f;
                if (sdv) {
                    if (r0 < p.nrows) sc0 = g_dinv[r0];
                    if (r1 < p.nrows) sc1 = g_dinv[r1];
                }
#pragma unroll
                for (int nt = 0; nt < 4; nt++) {
                    int c = wn * 32 + nt * 8 + (lane & 3) * 2;
                    if (c >= oc) continue;
                    float b0 = bs ? bs[c] : 0.f;
                    float b1 = bs ? bs[c + 1] : 0.f;
                    float d0 = acc[mt][nt][0] + b0;
                    float d1 = acc[mt][nt][1] + b1;
                    float d2 = acc[mt][nt][2] + b0;
                    float d3 = acc[mt][nt][3] + b1;
                    if (act == ACT_RELU) {
                        d0 = fmaxf(d0, 0.f); d1 = fmaxf(d1, 0.f);
                        d2 = fmaxf(d2, 0.f); d3 = fmaxf(d3, 0.f);
                    } else if (act == ACT_SIGM) {
                        d0 = 1.f / (1.f + expf(-d0));
                        d1 = 1.f / (1.f + expf(-d1));
                        d2 = 1.f / (1.f + expf(-d2));
                        d3 = 1.f / (1.f + expf(-d3));
                    }
                    d0 *= sc0; d1 *= sc0; d2 *= sc1; d3 *= sc1;
                    if (r0 < p.nrows) *(float2*)(outp + (size_t)r0 * ldc + c) = make_float2(d0, d1);
                    if (r1 < p.nrows) *(float2*)(outp + (size_t)r1 * ldc + c) = make_float2(d2, d3);
                }
            }
        }

        if (j + 1 < p.nout) {
            CPA_WAIT0();
            __syncthreads();
        }
    }
}

// ------------------- edge dtype detect + CSR build -------------------
__global__ void detect_k(const int* __restrict__ w, int nwords)
{
    __shared__ int any;
    if (threadIdx.x == 0) any = 0;
    __syncthreads();
    int npairs = min(nwords >> 1, 2048);
    for (int i = threadIdx.x; i < npairs; i += blockDim.x)
        if (w[2 * i + 1] != 0) atomicOr(&any, 1);
    __syncthreads();
    if (threadIdx.x == 0) g_is64 = (any == 0) ? 1 : 0;
}

__device__ __forceinline__ int edge_at(const void* ei, long long idx)
{
    return g_is64 ? (int)((const long long*)ei)[idx] : ((const int*)ei)[idx];
}

__global__ void hist_k(const void* __restrict__ ei, long long eoff, int ne)
{
    for (int e = blockIdx.x * blockDim.x + threadIdx.x; e < ne; e += gridDim.x * blockDim.x)
        atomicAdd(&g_deg[edge_at(ei, eoff + e)], 1);
}

__global__ void scan1(int n)
{
    __shared__ int wsum[32];
    int t = threadIdx.x;
    int idx = blockIdx.x * 4096 + t * 4;
    int v0 = (idx + 0 < n) ? g_deg[idx + 0] : 0;
    int v1 = (idx + 1 < n) ? g_deg[idx + 1] : 0;
    int v2 = (idx + 2 < n) ? g_deg[idx + 2] : 0;
    int v3 = (idx + 3 < n) ? g_deg[idx + 3] : 0;
    if (idx + 0 < n) g_dinv[idx + 0] = rsqrtf((float)(v0 + 1));
    if (idx + 1 < n) g_dinv[idx + 1] = rsqrtf((float)(v1 + 1));
    if (idx + 2 < n) g_dinv[idx + 2] = rsqrtf((float)(v2 + 1));
    if (idx + 3 < n) g_dinv[idx + 3] = rsqrtf((float)(v3 + 1));
    int tsum = v0 + v1 + v2 + v3;
    int lane = t & 31, w = t >> 5;
    int inc = tsum;
#pragma unroll
    for (int o = 1; o < 32; o <<= 1) {
        int y = __shfl_up_sync(0xffffffffu, inc, o);
        if (lane >= o) inc += y;
    }
    if (lane == 31) wsum[w] = inc;
    __syncthreads();
    if (w == 0) {
        int y = wsum[lane];
#pragma unroll
        for (int o = 1; o < 32; o <<= 1) {
            int z = __shfl_up_sync(0xffffffffu, y, o);
            if (lane >= o) y += z;
        }
        wsum[lane] = y;
    }
    __syncthreads();
    int excl = inc - tsum + (w > 0 ? wsum[w - 1] : 0);
    if (idx + 0 < n) g_rowp[idx + 0] = excl;
    if (idx + 1 < n) g_rowp[idx + 1] = excl + v0;
    if (idx + 2 < n) g_rowp[idx + 2] = excl + v0 + v1;
    if (idx + 3 < n) g_rowp[idx + 3] = excl + v0 + v1 + v2;
    if (t == 0) g_bsum[blockIdx.x] = wsum[31];
}

__global__ void scan2(int nb)
{
    if (threadIdx.x == 0 && blockIdx.x == 0) {
        int s = 0;
        for (int i = 0; i < nb; i++) { int t = g_bsum[i]; g_bsum[i] = s; s += t; }
    }
}

__global__ void scan3(int n, int total)
{
    int t = threadIdx.x;
    int idx = blockIdx.x * 4096 + t * 4;
    int off = g_bsum[blockIdx.x];
#pragma unroll
    for (int j = 0; j < 4; j++)
        if (idx + j < n) g_rowp[idx + j] += off;
    if (blockIdx.x == 0 && t == 0) g_rowp[n] = total;
}

__global__ void scatter_k(const void* __restrict__ ei, long long eoff, int ne)
{
    for (int e = blockIdx.x * blockDim.x + threadIdx.x; e < ne; e += gridDim.x * blockDim.x) {
        int d = edge_at(ei, eoff + e);
        int s = edge_at(ei, e);
        int pos = g_rowp[d] + atomicAdd(&g_fill[d], 1);
        g_col[pos] = s;
    }
}

// ------------------- kv = k^T v  (fp32, atomic finalize) + fused ksum -----------
__global__ __launch_bounds__(256)
void kv_k(const float* __restrict__ kk, const float* __restrict__ vv, int n)
{
    __shared__ float ks[32][128];
    __shared__ float vs[32][128];
    int t = threadIdx.x;
    int tx = t & 15, ty = t >> 4;
    int base = blockIdx.x * 512;
    int end = min(base + 512, n);

    int kcol = t & 127, krh = (t >> 7) * 16;
    float ksacc = 0.f;

    ull acc[4][8];
#pragma unroll
    for (int i = 0; i < 4; i++)
#pragma unroll
        for (int j = 0; j < 8; j++) acc[i][j] = 0ULL;

    for (int nb = base; nb < end; nb += 32) {
#pragma unroll
        for (int q = 0; q < 4; q++) {
            int idx = t + 256 * q;
            int r = idx >> 5, c = (idx & 31) * 4;
            int gr = nb + r;
            float4 a = make_float4(0, 0, 0, 0), b = make_float4(0, 0, 0, 0);
            if (gr < n) {
                a = *(const float4*)(kk + (size_t)gr * 128 + c);
                b = *(const float4*)(vv + (size_t)gr * 128 + c);
            }
            *(float4*)&ks[r][c] = a;
            *(float4*)&vs[r][c] = b;
        }
        __syncthreads();
#pragma unroll
        for (int r = 0; r < 16; r++) ksacc += ks[krh + r][kcol];
#pragma unroll 8
        for (int nn = 0; nn < 32; nn++) {
            ull a2[4];
            a2[0] = *(const ull*)&ks[nn][ty * 8 + 0];
            a2[1] = *(const ull*)&ks[nn][ty * 8 + 2];
            a2[2] = *(const ull*)&ks[nn][ty * 8 + 4];
            a2[3] = *(const ull*)&ks[nn][ty * 8 + 6];
            float b[8];
            *(float4*)&b[0] = *(const float4*)&vs[nn][tx * 8];
            *(float4*)&b[4] = *(const float4*)&vs[nn][tx * 8 + 4];
#pragma unroll
            for (int j = 0; j < 8; j++) {
                ull bd = pk2(b[j]);
#pragma unroll
                for (int i = 0; i < 4; i++) acc[i][j] = fma2(a2[i], bd, acc[i][j]);
            }
        }
        __syncthreads();
    }
#pragma unroll
    for (int i = 0; i < 4; i++)
#pragma unroll
        for (int j = 0; j < 8; j++) {
            float lo, hi;
            upk(acc[i][j], lo, hi);
            int d = ty * 8 + 2 * i, m = tx * 8 + j;
            atomicAdd(&g_kvs[d * 128 + m], lo);
            atomicAdd(&g_kvs[(d + 1) * 128 + m], hi);
        }
    ((float*)ks)[t] = ksacc;
    __syncthreads();
    if (t < 128) atomicAdd(&g_kvs[16384 + t], ksacc + ((float*)ks)[t + 128]);
}

// ------------------- fused SpMM + GCN-layer epilogue (warp per node) ------------
// g_xw holds y = xw * dinv (pre-scaled in GEMM epilogue)
// streaming data (lin, h, xloc, x) uses evict-first hints to keep xw L2-resident
__global__ __launch_bounds__(256)
void spmm_epi(const float* __restrict__ bg,
              const float* __restrict__ bng, const float* __restrict__ bnb,
              const float* __restrict__ bnrm, const float* __restrict__ bnrv,
              const float* __restrict__ lng, const float* __restrict__ lnb,
              int n, int first, int last)
{
    int w = (blockIdx.x * blockDim.x + threadIdx.x) >> 5;
    int lane = threadIdx.x & 31;
    if (w >= n) return;
    int c0 = lane * 4;

    float4 acc = *(const float4*)(g_xw + (size_t)w * 128 + c0);   // self term y_w
    int e0 = g_rowp[w], e1 = g_rowp[w + 1];
    int c_next = (e0 < e1) ? g_col[e0] : 0;
    for (int e = e0; e < e1; e++) {
        int c = c_next;
        if (e + 1 < e1) c_next = g_col[e + 1];
        float4 v = *(const float4*)(g_xw + (size_t)c * 128 + c0);
        acc.x += v.x; acc.y += v.y; acc.z += v.z; acc.w += v.w;
    }
    float di = g_dinv[w];
    float4 lv = ldcs4(g_lin + (size_t)w * 128 + c0);
    float4 xv;
    xv.x = acc.x * di + bg[c0 + 0] + lv.x;
    xv.y = acc.y * di + bg[c0 + 1] + lv.y;
    xv.z = acc.z * di + bg[c0 + 2] + lv.z;
    xv.w = acc.w * di + bg[c0 + 3] + lv.w;
#pragma unroll
    for (int j = 0; j < 4; j++) {
        float s = bng[c0 + j] * rsqrtf(bnrv[c0 + j] + 1e-5f);
        float* p = &xv.x + j;
        *p = fmaxf((*p - bnrm[c0 + j]) * s + bnb[c0 + j], 0.f);
    }
    float4 hv = ldcs4(g_h + (size_t)w * 128 + c0);
    float4 tv;
    tv.x = hv.x * xv.x; tv.y = hv.y * xv.y; tv.z = hv.z * xv.z; tv.w = hv.w * xv.w;
    float s1 = tv.x + tv.y + tv.z + tv.w;
    float s2 = tv.x * tv.x + tv.y * tv.y + tv.z * tv.z + tv.w * tv.w;
    s1 = wsumf(s1); s2 = wsumf(s2);
    float mu = s1 * (1.f / 128.f);
    float var = s2 * (1.f / 128.f) - mu * mu;
    float rs = rsqrtf(var + 1e-5f);
#pragma unroll
    for (int j = 0; j < 4; j++) {
        float* pt = &tv.x + j;
        float* px = &xv.x + j;
        float y = (*pt - mu) * rs * lng[c0 + j] + lnb[c0 + j];
        *px = 0.1f * y + 0.9f * (*px);
    }
    float4 xl = make_float4(0, 0, 0, 0);
    if (!first) xl = ldcs4(g_xloc + (size_t)w * 128 + c0);
    xl.x += xv.x; xl.y += xv.y; xl.z += xv.z; xl.w += xv.w;
    stcs4(g_xloc + (size_t)w * 128 + c0, xl);
    if (!last) stcs4(g_x + (size_t)w * 128 + c0, xv);
}

// ------------------- host orchestration -------------------
static inline void fill1(TCParams& p, int i, const __nv_bfloat16* bh, const __nv_bfloat16* bl,
                         const float* bias, float* out, int oc, int ldc, int act, int sdv = 0)
{
    p.bhi[i] = bh; p.blo[i] = bl; p.bias[i] = bias; p.out[i] = out;
    p.oc[i] = oc; p.ldc[i] = ldc; p.act[i] = act; p.sdinv[i] = sdv;
}

extern "C" void kernel_launch(void* const* d_in, const int* in_sizes, int n_in,
                              void* d_out, int out_size)
{
    const float* in_x  = (const float*)d_in[0];
    const void*  ei    = d_in[1];
    const float* Wh    = (const float*)d_in[2];
    const float* bh    = (const float*)d_in[3];
    const float* Wg    = (const float*)d_in[4];
    const float* bg    = (const float*)d_in[5];
    const float* Wl    = (const float*)d_in[6];
    const float* bl    = (const float*)d_in[7];
    const float* ln_g  = (const float*)d_in[8];
    const float* ln_b  = (const float*)d_in[9];
    const float* bn_g  = (const float*)d_in[10];
    const float* bn_b  = (const float*)d_in[11];
    const float* bn_rm = (const float*)d_in[12];
    const float* bn_rv = (const float*)d_in[13];
    const float* gWh   = (const float*)d_in[14];
    const float* gbh   = (const float*)d_in[15];
    const float* gWk   = (const float*)d_in[16];
    const float* gWv   = (const float*)d_in[17];
    const float* gln_g = (const float*)d_in[18];
    const float* gln_b = (const float*)d_in[19];
    const float* gWo   = (const float*)d_in[20];
    const float* gbo   = (const float*)d_in[21];
    const float* f_ln_g = (const float*)d_in[22];
    const float* f_ln_b = (const float*)d_in[23];
    const float* Wp    = (const float*)d_in[24];
    const float* bp    = (const float*)d_in[25];

    int n  = in_sizes[0] / 128;
    int ne = in_sizes[1] / 2;

    float *px, *ph, *pxw, *plin, *pxloc, *pxg, *pk, *pkvs;
    __nv_bfloat16 *pBhi, *pBlo;
    int *pdeg, *pfill;
    cudaGetSymbolAddress((void**)&px, g_x);
    cudaGetSymbolAddress((void**)&ph, g_h);
    cudaGetSymbolAddress((void**)&pxw, g_xw);
    cudaGetSymbolAddress((void**)&plin, g_lin);
    cudaGetSymbolAddress((void**)&pxloc, g_xloc);
    cudaGetSymbolAddress((void**)&pxg, g_xg);
    cudaGetSymbolAddress((void**)&pk, g_k);
    cudaGetSymbolAddress((void**)&pkvs, g_kvs);
    cudaGetSymbolAddress((void**)&pdeg, g_deg);
    cudaGetSymbolAddress((void**)&pfill, g_fill);
    cudaGetSymbolAddress((void**)&pBhi, g_Bhi);
    cudaGetSymbolAddress((void**)&pBlo, g_Blo);

    cudaFuncSetAttribute(gemm_tc, cudaFuncAttributeMaxDynamicSharedMemorySize, SMEM_TOTAL);

    int gg = (n + 127) / 128;
    int wg = (n * 32 + 255) / 256;
    int nblk = (n + 4095) / 4096;

    // launch order arranged so gemm_tc is profile index 5 (ncu -s 5 -c 1)
    prep_all<<<(30 * 16384 + 255) / 256, 256>>>(Wh, Wg, Wl, gWh, gWk, gWv, gWo, Wp, pBhi, pBlo);   // 0
    detect_k<<<1, 256>>>((const int*)ei, ne * 2);                                                   // 1
    cudaMemsetAsync(pdeg, 0, (size_t)n * 4);                                                        // 2
    hist_k<<<2048, 256>>>(ei, (long long)ne, ne);                                                   // 3
    scan1<<<nblk, 1024>>>(n);                                                                       // 4

    // first GEMM (layer 1) — A = in_x                                                              // 5
    {
        TCParams p = {};
        p.A = in_x; p.nrows = n; p.nout = 3; p.amode = AM_PLAIN;
        fill1(p, 0, pBhi + (size_t)0 * 16384,  pBlo + (size_t)0 * 16384,  bh, ph,   128, 128, ACT_RELU);
        fill1(p, 1, pBhi + (size_t)7 * 16384,  pBlo + (size_t)7 * 16384,  nullptr, pxw,  128, 128, ACT_NONE, 1);
        fill1(p, 2, pBhi + (size_t)14 * 16384, pBlo + (size_t)14 * 16384, bl, plin, 128, 128, ACT_NONE);
        gemm_tc<<<gg, 512, SMEM_TOTAL>>>(p);
    }

    scan2<<<1, 32>>>(nblk);
    scan3<<<nblk, 1024>>>(n, ne);
    cudaMemsetAsync(pfill, 0, (size_t)n * 4);
    scatter_k<<<2048, 256>>>(ei, (long long)ne, ne);

    spmm_epi<<<wg, 256>>>(bg, bn_g, bn_b, bn_rm, bn_rv, ln_g, ln_b, n, 1, 0);

    for (int i = 1; i < 7; i++) {
        TCParams p = {};
        p.A = px; p.nrows = n; p.nout = 3; p.amode = AM_PLAIN;
        fill1(p, 0, pBhi + (size_t)i * 16384,        pBlo + (size_t)i * 16384,        bh + i * 128, ph,   128, 128, ACT_RELU);
        fill1(p, 1, pBhi + (size_t)(7 + i) * 16384,  pBlo + (size_t)(7 + i) * 16384,  nullptr,      pxw,  128, 128, ACT_NONE, 1);
        fill1(p, 2, pBhi + (size_t)(14 + i) * 16384, pBlo + (size_t)(14 + i) * 16384, bl + i * 128, plin, 128, 128, ACT_NONE);
        gemm_tc<<<gg, 512, SMEM_TOTAL>>>(p);
        spmm_epi<<<wg, 256>>>(bg + i * 128, bn_g + i * 128, bn_b + i * 128,
                              bn_rm + i * 128, bn_rv + i * 128,
                              ln_g + i * 128, ln_b + i * 128, n, 0, i == 6);
    }

    // global attention (LN fused into first projection GEMM; attn_epi fused into out-GEMM)
    for (int j = 0; j < 2; j++) {
        {
            TCParams p = {};
            p.nrows = n; p.nout = 3;
            if (j == 0) { p.A = pxloc; p.amode = AM_LN; p.lng = f_ln_g; p.lnb = f_ln_b; }
            else        { p.A = pxg;   p.amode = AM_PLAIN; }
            fill1(p, 0, pBhi + (size_t)(21 + j) * 16384, pBlo + (size_t)(21 + j) * 16384, gbh + j * 128, ph,  128, 128, ACT_NONE);
            fill1(p, 1, pBhi + (size_t)(23 + j) * 16384, pBlo + (size_t)(23 + j) * 16384, nullptr,       pk,  128, 128, ACT_SIGM);
            fill1(p, 2, pBhi + (size_t)(25 + j) * 16384, pBlo + (size_t)(25 + j) * 16384, nullptr,       pxw, 128, 128, ACT_NONE);
            gemm_tc<<<gg, 512, SMEM_TOTAL>>>(p);
        }
        cudaMemsetAsync(pkvs, 0, (128 * 128 + 128) * 4);
        kv_k<<<(n + 511) / 512, 256>>>(pk, pxw, n);
        prep_kv<<<(16384 + 255) / 256, 256>>>(pBhi, pBlo);
        {
            TCParams p = {};
            p.A = pk; p.nrows = n; p.nout = 1; p.amode = AM_PLAIN;
            fill1(p, 0, pBhi + (size_t)30 * 16384, pBlo + (size_t)30 * 16384, nullptr, plin, 128, 128, ACT_NONE);
            gemm_tc<<<gg, 512, SMEM_TOTAL>>>(p);
        }
        {
            // out-GEMM with fused attention epilogue as A-transform
            TCParams p = {};
            p.A = plin; p.nrows = n; p.nout = 1; p.amode = AM_ATTN;
            p.lng = gln_g + j * 128; p.lnb = gln_b + j * 128;
            p.q = pk; p.hg = ph;
            fill1(p, 0, pBhi + (size_t)(27 + j) * 16384, pBlo + (size_t)(27 + j) * 16384, gbo + j * 128, pxg, 128, 128, ACT_RELU);
            gemm_tc<<<gg, 512, SMEM_TOTAL>>>(p);
        }
    }

    // final projection (oc=40)
    {
        TCParams p = {};
        p.A = pxg; p.nrows = n; p.nout = 1; p.amode = AM_PLAIN;
        fill1(p, 0, pBhi + (size_t)29 * 16384, pBlo + (size_t)29 * 16384, bp, (float*)d_out, 40, 40, ACT_NONE);
        gemm_tc<<<gg, 512, SMEM_TOTAL>>>(p);
    }
}

// round 16
// speedup vs baseline: 1.5943x; 1.0389x over previous
#include <cuda_runtime.h>
#include <cuda_bf16.h>
#include <cstddef>
#include <cstdint>

#define NMAX 100000
#define EMAX 1600000
#define CH 128

typedef unsigned long long ull;

// ------------------- device scratch (no allocations allowed) -------------------
__device__ __align__(16) float g_x   [NMAX * CH];
__device__ __align__(16) float g_h   [NMAX * CH];
__device__ __align__(16) float g_xw  [NMAX * CH];   // GCN: y = xw*dinv ; attn: v
__device__ __align__(16) float g_lin [NMAX * CH];   // also num
__device__ __align__(16) float g_xloc[NMAX * CH];
__device__ __align__(16) float g_xg  [NMAX * CH];
__device__ __align__(16) float g_k   [NMAX * CH];
__device__ __align__(16) float g_dinv[NMAX];
__device__ int   g_deg [NMAX];
__device__ int   g_rowp[NMAX + 1];
__device__ int   g_fill[NMAX];
__device__ int   g_col [EMAX];
__device__ int   g_bsum[64];
__device__ int   g_is64;
// kv [128][128] followed by ksum[128]
__device__ __align__(16) float g_kvs [CH * CH + CH];
// pre-split bf16 weights, row-major [n=128][k=128] per slot (slot 30 = kv)
__device__ __align__(16) __nv_bfloat16 g_Bhi[31 * 16384];
__device__ __align__(16) __nv_bfloat16 g_Blo[31 * 16384];

// ------------------- misc helpers -------------------
__device__ __forceinline__ float wsumf(float v) {
#pragma unroll
    for (int o = 16; o; o >>= 1) v += __shfl_xor_sync(0xffffffffu, v, o);
    return v;
}

// streaming (evict-first) load/store of float4
__device__ __forceinline__ float4 ldcs4(const float* p) {
    float4 v;
    asm volatile("ld.global.cs.v4.f32 {%0,%1,%2,%3}, [%4];"
                 : "=f"(v.x), "=f"(v.y), "=f"(v.z), "=f"(v.w) : "l"(p));
    return v;
}
__device__ __forceinline__ void stcs4(float* p, float4 v) {
    asm volatile("st.global.cs.v4.f32 [%0], {%1,%2,%3,%4};"
                 :: "l"(p), "f"(v.x), "f"(v.y), "f"(v.z), "f"(v.w));
}

// ------------------- mma / cp.async helpers -------------------
__device__ __forceinline__ uint32_t smem_u32(const void* p) {
    uint32_t a;
    asm("{ .reg .u64 t; cvta.to.shared.u64 t, %1; cvt.u32.u64 %0, t; }" : "=r"(a) : "l"(p));
    return a;
}
__device__ __forceinline__ void ldmat4(uint32_t& r0, uint32_t& r1, uint32_t& r2, uint32_t& r3,
                                       uint32_t addr) {
    asm volatile("ldmatrix.sync.aligned.m8n8.x4.shared.b16 {%0,%1,%2,%3}, [%4];"
                 : "=r"(r0), "=r"(r1), "=r"(r2), "=r"(r3) : "r"(addr));
}
__device__ __forceinline__ void ldmat4t(uint32_t& r0, uint32_t& r1, uint32_t& r2, uint32_t& r3,
                                        uint32_t addr) {
    asm volatile("ldmatrix.sync.aligned.m8n8.x4.trans.shared.b16 {%0,%1,%2,%3}, [%4];"
                 : "=r"(r0), "=r"(r1), "=r"(r2), "=r"(r3) : "r"(addr));
}
__device__ __forceinline__ void mma16816(float* d, const uint32_t* a, const uint32_t* b) {
    asm volatile(
        "mma.sync.aligned.m16n8k16.row.col.f32.bf16.bf16.f32 "
        "{%0,%1,%2,%3}, {%4,%5,%6,%7}, {%8,%9}, {%0,%1,%2,%3};"
        : "+f"(d[0]), "+f"(d[1]), "+f"(d[2]), "+f"(d[3])
        : "r"(a[0]), "r"(a[1]), "r"(a[2]), "r"(a[3]), "r"(b[0]), "r"(b[1]));
}
__device__ __forceinline__ void cpa16(uint32_t dst, const void* src) {
    asm volatile("cp.async.cg.shared.global [%0], [%1], 16;" :: "r"(dst), "l"(src));
}
#define CPA_COMMIT() asm volatile("cp.async.commit_group;" ::: "memory")
#define CPA_WAIT0()  asm volatile("cp.async.wait_group 0;" ::: "memory")

__device__ __forceinline__ void splitpack(float a, float b, uint32_t& hw, uint32_t& lw) {
    __nv_bfloat16 ha = __float2bfloat16(a), hb = __float2bfloat16(b);
    float ra = a - __bfloat162float(ha), rb = b - __bfloat162float(hb);
    __nv_bfloat16 la = __float2bfloat16(ra), lb = __float2bfloat16(rb);
    __nv_bfloat162 hv(ha, hb), lv(la, lb);
    hw = *(uint32_t*)&hv; lw = *(uint32_t*)&lv;
}

// ------------------- weight prep -------------------
__global__ void prep_all(const float* __restrict__ Wh, const float* __restrict__ Wg,
                         const float* __restrict__ Wl, const float* __restrict__ gWh,
                         const float* __restrict__ gWk, const float* __restrict__ gWv,
                         const float* __restrict__ gWo, const float* __restrict__ Wp,
                         __nv_bfloat16* __restrict__ dhi, __nv_bfloat16* __restrict__ dlo)
{
    int idx = blockIdx.x * blockDim.x + threadIdx.x;
    if (idx >= 30 * 16384) return;
    int s = idx >> 14;
    const float* src; int m; int oc = 128;
    if      (s < 7)  { src = Wh;  m = s; }
    else if (s < 14) { src = Wg;  m = s - 7; }
    else if (s < 21) { src = Wl;  m = s - 14; }
    else if (s < 23) { src = gWh; m = s - 21; }
    else if (s < 25) { src = gWk; m = s - 23; }
    else if (s < 27) { src = gWv; m = s - 25; }
    else if (s < 29) { src = gWo; m = s - 27; }
    else             { src = Wp;  m = 0; oc = 40; }
    int rem = idx & 16383, o = rem >> 7, k = rem & 127;
    float v = (o < oc) ? src[(size_t)m * oc * 128 + (size_t)o * 128 + k] : 0.f;
    __nv_bfloat16 hi = __float2bfloat16(v);
    dhi[idx] = hi;
    dlo[idx] = __float2bfloat16(v - __bfloat162float(hi));
}

__global__ void prep_kv(__nv_bfloat16* __restrict__ dhi, __nv_bfloat16* __restrict__ dlo)
{
    int idx = blockIdx.x * blockDim.x + threadIdx.x;
    if (idx >= 16384) return;
    int o = idx >> 7, k = idx & 127;
    float v = g_kvs[k * 128 + o];
    __nv_bfloat16 hi = __float2bfloat16(v);
    dhi[(size_t)30 * 16384 + idx] = hi;
    dlo[(size_t)30 * 16384 + idx] = __float2bfloat16(v - __bfloat162float(hi));
}

// ------------------- tensor-core GEMM: up to 3 products sharing A -------------------
#define ACT_NONE 0
#define ACT_RELU 1
#define ACT_SIGM 2

#define AM_PLAIN 0
#define AM_LN    1
#define AM_ATTN  2

struct TCParams {
    const float* A; int nrows; int nout; int amode;
    const float* lng; const float* lnb;          // LN / ATTN params
    const float* q; const float* hg;             // ATTN: q rows, gate rows
    const __nv_bfloat16* bhi[3]; const __nv_bfloat16* blo[3];
    const float* bias[3]; float* out[3];
    int oc[3]; int ldc[3]; int act[3]; int sdinv[3];
};

#define SA 136                       // smem row stride in bf16 elems (272B)
#define SM_TILE (128 * SA * 2)       // 34816 bytes per tile image
#define OFF_A_HI 0
#define OFF_A_LO SM_TILE
#define OFF_B(buf, img) ((uint32_t)(2 + (buf) * 2 + (img)) * SM_TILE)
#define SMEM_TOTAL (6 * SM_TILE)     // 208896 bytes

__global__ __launch_bounds__(512, 1) void gemm_tc(TCParams p)
{
    extern __shared__ __align__(16) char smem[];
    uint32_t sb = smem_u32(smem);
    int t = threadIdx.x;
    int lane = t & 31, wid = t >> 5;
    int wm = wid >> 2, wn = wid & 3;       // warp grid 4x4 -> warp tile 32x32
    int row0 = blockIdx.x * 128;

    // ---- prefetch B0 via cp.async (overlaps A conversion) ----
    {
        const char* sh = (const char*)p.bhi[0];
        const char* sl = (const char*)p.blo[0];
#pragma unroll
        for (int i = 0; i < 4; i++) {
            int idx = i * 512 + t;               // 2048 chunks of 16B per image
            int r = idx >> 4, c8 = (idx & 15) * 8;
            uint32_t boff = (uint32_t)r * (SA * 2) + c8 * 2;
            cpa16(sb + OFF_B(0, 0) + boff, sh + (size_t)idx * 16);
            cpa16(sb + OFF_B(0, 1) + boff, sl + (size_t)idx * 16);
        }
        CPA_COMMIT();
    }

    // ---- A load (+ optional fused row transform) + split to bf16 hi/lo ----
#pragma unroll
    for (int i = 0; i < 8; i++) {
        int r = i * 16 + wid;
        int gr = row0 + r;
        int c0 = lane * 4;
        float4 v = make_float4(0.f, 0.f, 0.f, 0.f);
        if (gr < p.nrows) v = *(const float4*)(p.A + (size_t)gr * 128 + c0);

        if (p.amode == AM_LN) {
            float s1 = v.x + v.y + v.z + v.w;
            float s2 = v.x * v.x + v.y * v.y + v.z * v.z + v.w * v.w;
            s1 = wsumf(s1); s2 = wsumf(s2);
            float mu = s1 * (1.f / 128.f);
            float var = s2 * (1.f / 128.f) - mu * mu;
            float rs = rsqrtf(var + 1e-5f);
            v.x = (v.x - mu) * rs * p.lng[c0 + 0] + p.lnb[c0 + 0];
            v.y = (v.y - mu) * rs * p.lng[c0 + 1] + p.lnb[c0 + 1];
            v.z = (v.z - mu) * rs * p.lng[c0 + 2] + p.lnb[c0 + 2];
            v.w = (v.w - mu) * rs * p.lng[c0 + 3] + p.lnb[c0 + 3];
        } else if (p.amode == AM_ATTN) {
            float4 qv = make_float4(0, 0, 0, 0), hv = qv;
            if (gr < p.nrows) {
                qv = *(const float4*)(p.q  + (size_t)gr * 128 + c0);
                hv = *(const float4*)(p.hg + (size_t)gr * 128 + c0);
            }
            float4 ksv = *(const float4*)(g_kvs + 16384 + c0);
            float den = qv.x * ksv.x + qv.y * ksv.y + qv.z * ksv.z + qv.w * ksv.w;
            den = wsumf(den);
            float inv = 1.f / (den + 1e-6f);
            v.x *= inv; v.y *= inv; v.z *= inv; v.w *= inv;
            float s1 = v.x + v.y + v.z + v.w;
            float s2 = v.x * v.x + v.y * v.y + v.z * v.z + v.w * v.w;
            s1 = wsumf(s1); s2 = wsumf(s2);
            float mu = s1 * (1.f / 128.f);
            float var = s2 * (1.f / 128.f) - mu * mu;
            float rs = rsqrtf(var + 1e-5f);
            v.x = ((v.x - mu) * rs * p.lng[c0 + 0] + p.lnb[c0 + 0]) * (hv.x + 0.9f);
            v.y = ((v.y - mu) * rs * p.lng[c0 + 1] + p.lnb[c0 + 1]) * (hv.y + 0.9f);
            v.z = ((v.z - mu) * rs * p.lng[c0 + 2] + p.lnb[c0 + 2]) * (hv.z + 0.9f);
            v.w = ((v.w - mu) * rs * p.lng[c0 + 3] + p.lnb[c0 + 3]) * (hv.w + 0.9f);
        }

        uint32_t h0, h1, l0, l1;
        splitpack(v.x, v.y, h0, l0);
        splitpack(v.z, v.w, h1, l1);
        uint32_t boff = (uint32_t)r * (SA * 2) + (uint32_t)c0 * 2;
        *(uint2*)(smem + OFF_A_HI + boff) = make_uint2(h0, h1);
        *(uint2*)(smem + OFF_A_LO + boff) = make_uint2(l0, l1);
    }
    CPA_WAIT0();
    __syncthreads();

    int g = lane >> 3, l7 = lane & 7;
    uint32_t a_row  = (uint32_t)(wm * 32 + (g & 1) * 8 + l7);
    uint32_t a_coff = (uint32_t)((g >> 1) * 8);
    uint32_t b_row  = (uint32_t)(wn * 32 + (g >> 1) * 8 + l7);
    uint32_t b_coff = (uint32_t)((g & 1) * 8);

    for (int j = 0; j < p.nout; j++) {
        if (j + 1 < p.nout) {
            const char* sh = (const char*)p.bhi[j + 1];
            const char* sl = (const char*)p.blo[j + 1];
            uint32_t bufh = OFF_B((j + 1) & 1, 0), bufl = OFF_B((j + 1) & 1, 1);
#pragma unroll
            for (int i = 0; i < 4; i++) {
                int idx = i * 512 + t;
                int r = idx >> 4, c8 = (idx & 15) * 8;
                uint32_t boff = (uint32_t)r * (SA * 2) + c8 * 2;
                cpa16(sb + bufh + boff, sh + (size_t)idx * 16);
                cpa16(sb + bufl + boff, sl + (size_t)idx * 16);
            }
            CPA_COMMIT();
        }

        float acc[2][4][4];
#pragma unroll
        for (int mt = 0; mt < 2; mt++)
#pragma unroll
            for (int nt = 0; nt < 4; nt++)
#pragma unroll
                for (int q2 = 0; q2 < 4; q2++) acc[mt][nt][q2] = 0.f;

        uint32_t obh = OFF_B(j & 1, 0), obl = OFF_B(j & 1, 1);
#pragma unroll
        for (int ks = 0; ks < 8; ks++) {
            uint32_t ah[2][4], al[2][4];
#pragma unroll
            for (int mt = 0; mt < 2; mt++) {
                uint32_t off = ((a_row + mt * 16) * SA + ks * 16 + a_coff) * 2;
                ldmat4(ah[mt][0], ah[mt][1], ah[mt][2], ah[mt][3], sb + OFF_A_HI + off);
                ldmat4(al[mt][0], al[mt][1], al[mt][2], al[mt][3], sb + OFF_A_LO + off);
            }
            uint32_t bh[4][2], bl[4][2];
#pragma unroll
            for (int np = 0; np < 2; np++) {
                uint32_t off = ((b_row + np * 16) * SA + ks * 16 + b_coff) * 2;
                ldmat4(bh[2 * np][0], bh[2 * np][1], bh[2 * np + 1][0], bh[2 * np + 1][1],
                       sb + obh + off);
                ldmat4(bl[2 * np][0], bl[2 * np][1], bl[2 * np + 1][0], bl[2 * np + 1][1],
                       sb + obl + off);
            }
#pragma unroll
            for (int mt = 0; mt < 2; mt++)
#pragma unroll
                for (int nt = 0; nt < 4; nt++) {
                    mma16816(acc[mt][nt], ah[mt], bh[nt]);
                    mma16816(acc[mt][nt], ah[mt], bl[nt]);
                    mma16816(acc[mt][nt], al[mt], bh[nt]);
                }
        }

        // ---- epilogue (register-only) ----
        {
            const float* bs = p.bias[j];
            float* outp = p.out[j];
            int oc = p.oc[j], ldc = p.ldc[j], act = p.act[j], sdv = p.sdinv[j];
#pragma unroll
            for (int mt = 0; mt < 2; mt++) {
                int r0 = row0 + wm * 32 + mt * 16 + (lane >> 2);
                int r1 = r0 + 8;
                float sc0 = 1.f, sc1 = 1.f;
                if (sdv) {
                    if (r0 < p.nrows) sc0 = g_dinv[r0];
                    if (r1 < p.nrows) sc1 = g_dinv[r1];
                }
#pragma unroll
                for (int nt = 0; nt < 4; nt++) {
                    int c = wn * 32 + nt * 8 + (lane & 3) * 2;
                    if (c >= oc) continue;
                    float b0 = bs ? bs[c] : 0.f;
                    float b1 = bs ? bs[c + 1] : 0.f;
                    float d0 = acc[mt][nt][0] + b0;
                    float d1 = acc[mt][nt][1] + b1;
                    float d2 = acc[mt][nt][2] + b0;
                    float d3 = acc[mt][nt][3] + b1;
                    if (act == ACT_RELU) {
                        d0 = fmaxf(d0, 0.f); d1 = fmaxf(d1, 0.f);
                        d2 = fmaxf(d2, 0.f); d3 = fmaxf(d3, 0.f);
                    } else if (act == ACT_SIGM) {
                        d0 = 1.f / (1.f + expf(-d0));
                        d1 = 1.f / (1.f + expf(-d1));
                        d2 = 1.f / (1.f + expf(-d2));
                        d3 = 1.f / (1.f + expf(-d3));
                    }
                    d0 *= sc0; d1 *= sc0; d2 *= sc1; d3 *= sc1;
                    if (r0 < p.nrows) *(float2*)(outp + (size_t)r0 * ldc + c) = make_float2(d0, d1);
                    if (r1 < p.nrows) *(float2*)(outp + (size_t)r1 * ldc + c) = make_float2(d2, d3);
                }
            }
        }

        if (j + 1 < p.nout) {
            CPA_WAIT0();
            __syncthreads();
        }
    }
}

// ------------------- edge dtype detect + CSR build -------------------
__global__ void detect_k(const int* __restrict__ w, int nwords)
{
    __shared__ int any;
    if (threadIdx.x == 0) any = 0;
    __syncthreads();
    int npairs = min(nwords >> 1, 2048);
    for (int i = threadIdx.x; i < npairs; i += blockDim.x)
        if (w[2 * i + 1] != 0) atomicOr(&any, 1);
    __syncthreads();
    if (threadIdx.x == 0) g_is64 = (any == 0) ? 1 : 0;
}

__device__ __forceinline__ int edge_at(const void* ei, long long idx)
{
    return g_is64 ? (int)((const long long*)ei)[idx] : ((const int*)ei)[idx];
}

__global__ void hist_k(const void* __restrict__ ei, long long eoff, int ne)
{
    for (int e = blockIdx.x * blockDim.x + threadIdx.x; e < ne; e += gridDim.x * blockDim.x)
        atomicAdd(&g_deg[edge_at(ei, eoff + e)], 1);
}

__global__ void scan1(int n)
{
    __shared__ int wsum[32];
    int t = threadIdx.x;
    int idx = blockIdx.x * 4096 + t * 4;
    int v0 = (idx + 0 < n) ? g_deg[idx + 0] : 0;
    int v1 = (idx + 1 < n) ? g_deg[idx + 1] : 0;
    int v2 = (idx + 2 < n) ? g_deg[idx + 2] : 0;
    int v3 = (idx + 3 < n) ? g_deg[idx + 3] : 0;
    if (idx + 0 < n) g_dinv[idx + 0] = rsqrtf((float)(v0 + 1));
    if (idx + 1 < n) g_dinv[idx + 1] = rsqrtf((float)(v1 + 1));
    if (idx + 2 < n) g_dinv[idx + 2] = rsqrtf((float)(v2 + 1));
    if (idx + 3 < n) g_dinv[idx + 3] = rsqrtf((float)(v3 + 1));
    int tsum = v0 + v1 + v2 + v3;
    int lane = t & 31, w = t >> 5;
    int inc = tsum;
#pragma unroll
    for (int o = 1; o < 32; o <<= 1) {
        int y = __shfl_up_sync(0xffffffffu, inc, o);
        if (lane >= o) inc += y;
    }
    if (lane == 31) wsum[w] = inc;
    __syncthreads();
    if (w == 0) {
        int y = wsum[lane];
#pragma unroll
        for (int o = 1; o < 32; o <<= 1) {
            int z = __shfl_up_sync(0xffffffffu, y, o);
            if (lane >= o) y += z;
        }
        wsum[lane] = y;
    }
    __syncthreads();
    int excl = inc - tsum + (w > 0 ? wsum[w - 1] : 0);
    if (idx + 0 < n) g_rowp[idx + 0] = excl;
    if (idx + 1 < n) g_rowp[idx + 1] = excl + v0;
    if (idx + 2 < n) g_rowp[idx + 2] = excl + v0 + v1;
    if (idx + 3 < n) g_rowp[idx + 3] = excl + v0 + v1 + v2;
    if (t == 0) g_bsum[blockIdx.x] = wsum[31];
}

__global__ void scan2(int nb)
{
    if (threadIdx.x == 0 && blockIdx.x == 0) {
        int s = 0;
        for (int i = 0; i < nb; i++) { int t = g_bsum[i]; g_bsum[i] = s; s += t; }
    }
}

__global__ void scan3(int n, int total)
{
    int t = threadIdx.x;
    int idx = blockIdx.x * 4096 + t * 4;
    int off = g_bsum[blockIdx.x];
#pragma unroll
    for (int j = 0; j < 4; j++)
        if (idx + j < n) g_rowp[idx + j] += off;
    if (blockIdx.x == 0 && t == 0) g_rowp[n] = total;
}

__global__ void scatter_k(const void* __restrict__ ei, long long eoff, int ne)
{
    for (int e = blockIdx.x * blockDim.x + threadIdx.x; e < ne; e += gridDim.x * blockDim.x) {
        int d = edge_at(ei, eoff + e);
        int s = edge_at(ei, e);
        int pos = g_rowp[d] + atomicAdd(&g_fill[d], 1);
        g_col[pos] = s;
    }
}

// ------------------- kv = k^T v via HMMA (3-term split-bf16) + fused ksum -------
// D[h][m] = sum_n k[n][h] * v[n][m]; smem holds chunk [n=16][128] row-major;
// both operands are logically transposed -> ldmatrix.trans with swapped g-bit roles.
__global__ __launch_bounds__(512) void kv_tc(const float* __restrict__ kk,
                                             const float* __restrict__ vv, int n)
{
    __shared__ __align__(16) __nv_bfloat16 skh[16][SA], skl[16][SA];
    __shared__ __align__(16) __nv_bfloat16 svh[16][SA], svl[16][SA];
    __shared__ float kss[128];
    int t = threadIdx.x, lane = t & 31, wid = t >> 5;
    int wm = wid >> 2, wn = wid & 3;
    int base = blockIdx.x * 512;
    int rows = min(512, n - base);
    int nch = (rows + 15) >> 4;

    if (t < 128) kss[t] = 0.f;

    int lr = wid;               // load row 0..15
    int c4 = lane * 4;          // load col group

    uint32_t kh_b = smem_u32(&skh[0][0]);
    uint32_t kl_b = smem_u32(&skl[0][0]);
    uint32_t vh_b = smem_u32(&svh[0][0]);
    uint32_t vl_b = smem_u32(&svl[0][0]);

    int g = lane >> 3, l7 = lane & 7;
    // trans mappings (g-bit roles swapped vs non-trans)
    uint32_t a_off = (uint32_t)((g >> 1) * 8 + l7) * (SA * 2) + (uint32_t)(wm * 32 + (g & 1) * 8) * 2;
    uint32_t b_off = (uint32_t)((g & 1) * 8 + l7) * (SA * 2) + (uint32_t)(wn * 32 + (g >> 1) * 8) * 2;

    float acc[2][4][4];
#pragma unroll
    for (int mt = 0; mt < 2; mt++)
#pragma unroll
        for (int nt = 0; nt < 4; nt++)
#pragma unroll
            for (int q = 0; q < 4; q++) acc[mt][nt][q] = 0.f;

    float4 ksacc = make_float4(0.f, 0.f, 0.f, 0.f);

    // preload chunk 0
    float4 kreg = make_float4(0, 0, 0, 0), vreg = kreg;
    {
        int gr = base + lr;
        if (gr < n) {
            kreg = *(const float4*)(kk + (size_t)gr * 128 + c4);
            vreg = *(const float4*)(vv + (size_t)gr * 128 + c4);
        }
    }

    for (int c = 0; c < nch; c++) {
        __syncthreads();   // previous mma done; smem reusable
        // store + split
        uint32_t h0, h1, l0, l1;
        splitpack(kreg.x, kreg.y, h0, l0);
        splitpack(kreg.z, kreg.w, h1, l1);
        *(uint2*)&skh[lr][c4] = make_uint2(h0, h1);
        *(uint2*)&skl[lr][c4] = make_uint2(l0, l1);
        ksacc.x += kreg.x; ksacc.y += kreg.y; ksacc.z += kreg.z; ksacc.w += kreg.w;
        splitpack(vreg.x, vreg.y, h0, l0);
        splitpack(vreg.z, vreg.w, h1, l1);
        *(uint2*)&svh[lr][c4] = make_uint2(h0, h1);
        *(uint2*)&svl[lr][c4] = make_uint2(l0, l1);
        // preload next chunk
        if (c + 1 < nch) {
            int gr = base + (c + 1) * 16 + lr;
            kreg = vreg = make_float4(0, 0, 0, 0);
            if (gr < n) {
                kreg = *(const float4*)(kk + (size_t)gr * 128 + c4);
                vreg = *(const float4*)(vv + (size_t)gr * 128 + c4);
            }
        }
        __syncthreads();
        // fragments (single k16 step per chunk)
        uint32_t ah[2][4], al[2][4];
#pragma unroll
        for (int mt = 0; mt < 2; mt++) {
            ldmat4t(ah[mt][0], ah[mt][1], ah[mt][2], ah[mt][3], kh_b + a_off + mt * 32);
            ldmat4t(al[mt][0], al[mt][1], al[mt][2], al[mt][3], kl_b + a_off + mt * 32);
        }
        uint32_t bh[4][2], bl[4][2];
#pragma unroll
        for (int np = 0; np < 2; np++) {
            ldmat4t(bh[2 * np][0], bh[2 * np][1], bh[2 * np + 1][0], bh[2 * np + 1][1],
                    vh_b + b_off + np * 32);
            ldmat4t(bl[2 * np][0], bl[2 * np][1], bl[2 * np + 1][0], bl[2 * np + 1][1],
                    vl_b + b_off + np * 32);
        }
#pragma unroll
        for (int mt = 0; mt < 2; mt++)
#pragma unroll
            for (int nt = 0; nt < 4; nt++) {
                mma16816(acc[mt][nt], ah[mt], bh[nt]);
                mma16816(acc[mt][nt], ah[mt], bl[nt]);
                mma16816(acc[mt][nt], al[mt], bh[nt]);
            }
    }

    // finalize kv atomically
#pragma unroll
    for (int mt = 0; mt < 2; mt++) {
        int r0 = wm * 32 + mt * 16 + (lane >> 2);
        int r1 = r0 + 8;
#pragma unroll
        for (int nt = 0; nt < 4; nt++) {
            int cc = wn * 32 + nt * 8 + (lane & 3) * 2;
            atomicAdd(&g_kvs[r0 * 128 + cc],     acc[mt][nt][0]);
            atomicAdd(&g_kvs[r0 * 128 + cc + 1], acc[mt][nt][1]);
            atomicAdd(&g_kvs[r1 * 128 + cc],     acc[mt][nt][2]);
            atomicAdd(&g_kvs[r1 * 128 + cc + 1], acc[mt][nt][3]);
        }
    }
    // ksum: smem reduce then one global atomic per column
    atomicAdd(&kss[c4 + 0], ksacc.x);
    atomicAdd(&kss[c4 + 1], ksacc.y);
    atomicAdd(&kss[c4 + 2], ksacc.z);
    atomicAdd(&kss[c4 + 3], ksacc.w);
    __syncthreads();
    if (t < 128) atomicAdd(&g_kvs[16384 + t], kss[t]);
}

// ------------------- fused SpMM + GCN-layer epilogue (warp per node) ------------
// g_xw holds y = xw * dinv (pre-scaled in GEMM epilogue)
// streaming data (lin, h, xloc, x) uses evict-first hints to keep xw L2-resident
__global__ __launch_bounds__(256)
void spmm_epi(const float* __restrict__ bg,
              const float* __restrict__ bng, const float* __restrict__ bnb,
              const float* __restrict__ bnrm, const float* __restrict__ bnrv,
              const float* __restrict__ lng, const float* __restrict__ lnb,
              int n, int first, int last)
{
    int w = (blockIdx.x * blockDim.x + threadIdx.x) >> 5;
    int lane = threadIdx.x & 31;
    if (w >= n) return;
    int c0 = lane * 4;

    float4 acc = *(const float4*)(g_xw + (size_t)w * 128 + c0);   // self term y_w
    int e0 = g_rowp[w], e1 = g_rowp[w + 1];
    int c_next = (e0 < e1) ? g_col[e0] : 0;
    for (int e = e0; e < e1; e++) {
        int c = c_next;
        if (e + 1 < e1) c_next = g_col[e + 1];
        float4 v = *(const float4*)(g_xw + (size_t)c * 128 + c0);
        acc.x += v.x; acc.y += v.y; acc.z += v.z; acc.w += v.w;
    }
    float di = g_dinv[w];
    float4 lv = ldcs4(g_lin + (size_t)w * 128 + c0);
    float4 xv;
    xv.x = acc.x * di + bg[c0 + 0] + lv.x;
    xv.y = acc.y * di + bg[c0 + 1] + lv.y;
    xv.z = acc.z * di + bg[c0 + 2] + lv.z;
    xv.w = acc.w * di + bg[c0 + 3] + lv.w;
#pragma unroll
    for (int j = 0; j < 4; j++) {
        float s = bng[c0 + j] * rsqrtf(bnrv[c0 + j] + 1e-5f);
        float* p = &xv.x + j;
        *p = fmaxf((*p - bnrm[c0 + j]) * s + bnb[c0 + j], 0.f);
    }
    float4 hv = ldcs4(g_h + (size_t)w * 128 + c0);
    float4 tv;
    tv.x = hv.x * xv.x; tv.y = hv.y * xv.y; tv.z = hv.z * xv.z; tv.w = hv.w * xv.w;
    float s1 = tv.x + tv.y + tv.z + tv.w;
    float s2 = tv.x * tv.x + tv.y * tv.y + tv.z * tv.z + tv.w * tv.w;
    s1 = wsumf(s1); s2 = wsumf(s2);
    float mu = s1 * (1.f / 128.f);
    float var = s2 * (1.f / 128.f) - mu * mu;
    float rs = rsqrtf(var + 1e-5f);
#pragma unroll
    for (int j = 0; j < 4; j++) {
        float* pt = &tv.x + j;
        float* px = &xv.x + j;
        float y = (*pt - mu) * rs * lng[c0 + j] + lnb[c0 + j];
        *px = 0.1f * y + 0.9f * (*px);
    }
    float4 xl = make_float4(0, 0, 0, 0);
    if (!first) xl = ldcs4(g_xloc + (size_t)w * 128 + c0);
    xl.x += xv.x; xl.y += xv.y; xl.z += xv.z; xl.w += xv.w;
    stcs4(g_xloc + (size_t)w * 128 + c0, xl);
    if (!last) stcs4(g_x + (size_t)w * 128 + c0, xv);
}

// ------------------- host orchestration -------------------
static inline void fill1(TCParams& p, int i, const __nv_bfloat16* bh, const __nv_bfloat16* bl,
                         const float* bias, float* out, int oc, int ldc, int act, int sdv = 0)
{
    p.bhi[i] = bh; p.blo[i] = bl; p.bias[i] = bias; p.out[i] = out;
    p.oc[i] = oc; p.ldc[i] = ldc; p.act[i] = act; p.sdinv[i] = sdv;
}

extern "C" void kernel_launch(void* const* d_in, const int* in_sizes, int n_in,
                              void* d_out, int out_size)
{
    const float* in_x  = (const float*)d_in[0];
    const void*  ei    = d_in[1];
    const float* Wh    = (const float*)d_in[2];
    const float* bh    = (const float*)d_in[3];
    const float* Wg    = (const float*)d_in[4];
    const float* bg    = (const float*)d_in[5];
    const float* Wl    = (const float*)d_in[6];
    const float* bl    = (const float*)d_in[7];
    const float* ln_g  = (const float*)d_in[8];
    const float* ln_b  = (const float*)d_in[9];
    const float* bn_g  = (const float*)d_in[10];
    const float* bn_b  = (const float*)d_in[11];
    const float* bn_rm = (const float*)d_in[12];
    const float* bn_rv = (const float*)d_in[13];
    const float* gWh   = (const float*)d_in[14];
    const float* gbh   = (const float*)d_in[15];
    const float* gWk   = (const float*)d_in[16];
    const float* gWv   = (const float*)d_in[17];
    const float* gln_g = (const float*)d_in[18];
    const float* gln_b = (const float*)d_in[19];
    const float* gWo   = (const float*)d_in[20];
    const float* gbo   = (const float*)d_in[21];
    const float* f_ln_g = (const float*)d_in[22];
    const float* f_ln_b = (const float*)d_in[23];
    const float* Wp    = (const float*)d_in[24];
    const float* bp    = (const float*)d_in[25];

    int n  = in_sizes[0] / 128;
    int ne = in_sizes[1] / 2;

    float *px, *ph, *pxw, *plin, *pxloc, *pxg, *pk, *pkvs;
    __nv_bfloat16 *pBhi, *pBlo;
    int *pdeg, *pfill;
    cudaGetSymbolAddress((void**)&px, g_x);
    cudaGetSymbolAddress((void**)&ph, g_h);
    cudaGetSymbolAddress((void**)&pxw, g_xw);
    cudaGetSymbolAddress((void**)&plin, g_lin);
    cudaGetSymbolAddress((void**)&pxloc, g_xloc);
    cudaGetSymbolAddress((void**)&pxg, g_xg);
    cudaGetSymbolAddress((void**)&pk, g_k);
    cudaGetSymbolAddress((void**)&pkvs, g_kvs);
    cudaGetSymbolAddress((void**)&pdeg, g_deg);
    cudaGetSymbolAddress((void**)&pfill, g_fill);
    cudaGetSymbolAddress((void**)&pBhi, g_Bhi);
    cudaGetSymbolAddress((void**)&pBlo, g_Blo);

    cudaFuncSetAttribute(gemm_tc, cudaFuncAttributeMaxDynamicSharedMemorySize, SMEM_TOTAL);

    int gg = (n + 127) / 128;
    int wg = (n * 32 + 255) / 256;
    int nblk = (n + 4095) / 4096;

    prep_all<<<(30 * 16384 + 255) / 256, 256>>>(Wh, Wg, Wl, gWh, gWk, gWv, gWo, Wp, pBhi, pBlo);
    detect_k<<<1, 256>>>((const int*)ei, ne * 2);
    cudaMemsetAsync(pdeg, 0, (size_t)n * 4);
    hist_k<<<2048, 256>>>(ei, (long long)ne, ne);
    scan1<<<nblk, 1024>>>(n);

    // first GEMM (layer 1) — A = in_x
    {
        TCParams p = {};
        p.A = in_x; p.nrows = n; p.nout = 3; p.amode = AM_PLAIN;
        fill1(p, 0, pBhi + (size_t)0 * 16384,  pBlo + (size_t)0 * 16384,  bh, ph,   128, 128, ACT_RELU);
        fill1(p, 1, pBhi + (size_t)7 * 16384,  pBlo + (size_t)7 * 16384,  nullptr, pxw,  128, 128, ACT_NONE, 1);
        fill1(p, 2, pBhi + (size_t)14 * 16384, pBlo + (size_t)14 * 16384, bl, plin, 128, 128, ACT_NONE);
        gemm_tc<<<gg, 512, SMEM_TOTAL>>>(p);
    }

    scan2<<<1, 32>>>(nblk);
    scan3<<<nblk, 1024>>>(n, ne);
    cudaMemsetAsync(pfill, 0, (size_t)n * 4);
    scatter_k<<<2048, 256>>>(ei, (long long)ne, ne);

    spmm_epi<<<wg, 256>>>(bg, bn_g, bn_b, bn_rm, bn_rv, ln_g, ln_b, n, 1, 0);

    for (int i = 1; i < 7; i++) {
        TCParams p = {};
        p.A = px; p.nrows = n; p.nout = 3; p.amode = AM_PLAIN;
        fill1(p, 0, pBhi + (size_t)i * 16384,        pBlo + (size_t)i * 16384,        bh + i * 128, ph,   128, 128, ACT_RELU);
        fill1(p, 1, pBhi + (size_t)(7 + i) * 16384,  pBlo + (size_t)(7 + i) * 16384,  nullptr,      pxw,  128, 128, ACT_NONE, 1);
        fill1(p, 2, pBhi + (size_t)(14 + i) * 16384, pBlo + (size_t)(14 + i) * 16384, bl + i * 128, plin, 128, 128, ACT_NONE);
        gemm_tc<<<gg, 512, SMEM_TOTAL>>>(p);
        spmm_epi<<<wg, 256>>>(bg + i * 128, bn_g + i * 128, bn_b + i * 128,
                              bn_rm + i * 128, bn_rv + i * 128,
                              ln_g + i * 128, ln_b + i * 128, n, 0, i == 6);
    }

    // global attention (LN fused into first projection GEMM; attn_epi fused into out-GEMM)
    for (int j = 0; j < 2; j++) {
        {
            TCParams p = {};
            p.nrows = n; p.nout = 3;
            if (j == 0) { p.A = pxloc; p.amode = AM_LN; p.lng = f_ln_g; p.lnb = f_ln_b; }
            else        { p.A = pxg;   p.amode = AM_PLAIN; }
            fill1(p, 0, pBhi + (size_t)(21 + j) * 16384, pBlo + (size_t)(21 + j) * 16384, gbh + j * 128, ph,  128, 128, ACT_NONE);
            fill1(p, 1, pBhi + (size_t)(23 + j) * 16384, pBlo + (size_t)(23 + j) * 16384, nullptr,       pk,  128, 128, ACT_SIGM);
            fill1(p, 2, pBhi + (size_t)(25 + j) * 16384, pBlo + (size_t)(25 + j) * 16384, nullptr,       pxw, 128, 128, ACT_NONE);
            gemm_tc<<<gg, 512, SMEM_TOTAL>>>(p);
        }
        cudaMemsetAsync(pkvs, 0, (128 * 128 + 128) * 4);
        kv_tc<<<(n + 511) / 512, 512>>>(pk, pxw, n);
        prep_kv<<<(16384 + 255) / 256, 256>>>(pBhi, pBlo);
        {
            TCParams p = {};
            p.A = pk; p.nrows = n; p.nout = 1; p.amode = AM_PLAIN;
            fill1(p, 0, pBhi + (size_t)30 * 16384, pBlo + (size_t)30 * 16384, nullptr, plin, 128, 128, ACT_NONE);
            gemm_tc<<<gg, 512, SMEM_TOTAL>>>(p);
        }
        {
            // out-GEMM with fused attention epilogue as A-transform
            TCParams p = {};
            p.A = plin; p.nrows = n; p.nout = 1; p.amode = AM_ATTN;
            p.lng = gln_g + j * 128; p.lnb = gln_b + j * 128;
            p.q = pk; p.hg = ph;
            fill1(p, 0, pBhi + (size_t)(27 + j) * 16384, pBlo + (size_t)(27 + j) * 16384, gbo + j * 128, pxg, 128, 128, ACT_RELU);
            gemm_tc<<<gg, 512, SMEM_TOTAL>>>(p);
        }
    }

    // final projection (oc=40)
    {
        TCParams p = {};
        p.A = pxg; p.nrows = n; p.nout = 1; p.amode = AM_PLAIN;
        fill1(p, 0, pBhi + (size_t)29 * 16384, pBlo + (size_t)29 * 16384, bp, (float*)d_out, 40, 40, ACT_NONE);
        gemm_tc<<<gg, 512, SMEM_TOTAL>>>(p);
    }
}

// round 17
// speedup vs baseline: 1.6034x; 1.0057x over previous
#include <cuda_runtime.h>
#include <cuda_bf16.h>
#include <cstddef>
#include <cstdint>

#define NMAX 100000
#define EMAX 1600000
#define CH 128

typedef unsigned long long ull;

// ------------------- device scratch (no allocations allowed) -------------------
__device__ __align__(16) float g_x   [NMAX * CH];
__device__ __align__(16) float g_h   [NMAX * CH];
__device__ __align__(16) float g_xw  [NMAX * CH];   // GCN: y = xw*dinv ; attn: v
__device__ __align__(16) float g_lin [NMAX * CH];   // also num
__device__ __align__(16) float g_xloc[NMAX * CH];
__device__ __align__(16) float g_xg  [NMAX * CH];
__device__ __align__(16) float g_k   [NMAX * CH];
__device__ __align__(16) float g_dinv[NMAX];
__device__ int   g_deg [NMAX];
__device__ int   g_rowp[NMAX + 1];
__device__ int   g_fill[NMAX];
__device__ int   g_col [EMAX];
__device__ int   g_bsum[64];
__device__ int   g_is64;
// kv [128][128] followed by ksum[128]
__device__ __align__(16) float g_kvs [CH * CH + CH];
// pre-split bf16 weights, row-major [n=128][k=128] per slot (slot 30 = kv)
__device__ __align__(16) __nv_bfloat16 g_Bhi[31 * 16384];
__device__ __align__(16) __nv_bfloat16 g_Blo[31 * 16384];

// ------------------- misc helpers -------------------
__device__ __forceinline__ float wsumf(float v) {
#pragma unroll
    for (int o = 16; o; o >>= 1) v += __shfl_xor_sync(0xffffffffu, v, o);
    return v;
}

// streaming (evict-first) load/store
__device__ __forceinline__ float4 ldcs4(const float* p) {
    float4 v;
    asm volatile("ld.global.cs.v4.f32 {%0,%1,%2,%3}, [%4];"
                 : "=f"(v.x), "=f"(v.y), "=f"(v.z), "=f"(v.w) : "l"(p));
    return v;
}
__device__ __forceinline__ void stcs4(float* p, float4 v) {
    asm volatile("st.global.cs.v4.f32 [%0], {%1,%2,%3,%4};"
                 :: "l"(p), "f"(v.x), "f"(v.y), "f"(v.z), "f"(v.w));
}
__device__ __forceinline__ void stcs2(float* p, float a, float b) {
    asm volatile("st.global.cs.v2.f32 [%0], {%1,%2};" :: "l"(p), "f"(a), "f"(b));
}

// ------------------- mma / cp.async helpers -------------------
__device__ __forceinline__ uint32_t smem_u32(const void* p) {
    uint32_t a;
    asm("{ .reg .u64 t; cvta.to.shared.u64 t, %1; cvt.u32.u64 %0, t; }" : "=r"(a) : "l"(p));
    return a;
}
__device__ __forceinline__ void ldmat4(uint32_t& r0, uint32_t& r1, uint32_t& r2, uint32_t& r3,
                                       uint32_t addr) {
    asm volatile("ldmatrix.sync.aligned.m8n8.x4.shared.b16 {%0,%1,%2,%3}, [%4];"
                 : "=r"(r0), "=r"(r1), "=r"(r2), "=r"(r3) : "r"(addr));
}
__device__ __forceinline__ void ldmat4t(uint32_t& r0, uint32_t& r1, uint32_t& r2, uint32_t& r3,
                                        uint32_t addr) {
    asm volatile("ldmatrix.sync.aligned.m8n8.x4.trans.shared.b16 {%0,%1,%2,%3}, [%4];"
                 : "=r"(r0), "=r"(r1), "=r"(r2), "=r"(r3) : "r"(addr));
}
__device__ __forceinline__ void mma16816(float* d, const uint32_t* a, const uint32_t* b) {
    asm volatile(
        "mma.sync.aligned.m16n8k16.row.col.f32.bf16.bf16.f32 "
        "{%0,%1,%2,%3}, {%4,%5,%6,%7}, {%8,%9}, {%0,%1,%2,%3};"
        : "+f"(d[0]), "+f"(d[1]), "+f"(d[2]), "+f"(d[3])
        : "r"(a[0]), "r"(a[1]), "r"(a[2]), "r"(a[3]), "r"(b[0]), "r"(b[1]));
}
__device__ __forceinline__ void cpa16(uint32_t dst, const void* src) {
    asm volatile("cp.async.cg.shared.global [%0], [%1], 16;" :: "r"(dst), "l"(src));
}
#define CPA_COMMIT() asm volatile("cp.async.commit_group;" ::: "memory")
#define CPA_WAIT0()  asm volatile("cp.async.wait_group 0;" ::: "memory")

__device__ __forceinline__ void splitpack(float a, float b, uint32_t& hw, uint32_t& lw) {
    __nv_bfloat16 ha = __float2bfloat16(a), hb = __float2bfloat16(b);
    float ra = a - __bfloat162float(ha), rb = b - __bfloat162float(hb);
    __nv_bfloat16 la = __float2bfloat16(ra), lb = __float2bfloat16(rb);
    __nv_bfloat162 hv(ha, hb), lv(la, lb);
    hw = *(uint32_t*)&hv; lw = *(uint32_t*)&lv;
}

// ------------------- weight prep -------------------
__global__ void prep_all(const float* __restrict__ Wh, const float* __restrict__ Wg,
                         const float* __restrict__ Wl, const float* __restrict__ gWh,
                         const float* __restrict__ gWk, const float* __restrict__ gWv,
                         const float* __restrict__ gWo, const float* __restrict__ Wp,
                         __nv_bfloat16* __restrict__ dhi, __nv_bfloat16* __restrict__ dlo)
{
    int idx = blockIdx.x * blockDim.x + threadIdx.x;
    if (idx >= 30 * 16384) return;
    int s = idx >> 14;
    const float* src; int m; int oc = 128;
    if      (s < 7)  { src = Wh;  m = s; }
    else if (s < 14) { src = Wg;  m = s - 7; }
    else if (s < 21) { src = Wl;  m = s - 14; }
    else if (s < 23) { src = gWh; m = s - 21; }
    else if (s < 25) { src = gWk; m = s - 23; }
    else if (s < 27) { src = gWv; m = s - 25; }
    else if (s < 29) { src = gWo; m = s - 27; }
    else             { src = Wp;  m = 0; oc = 40; }
    int rem = idx & 16383, o = rem >> 7, k = rem & 127;
    float v = (o < oc) ? src[(size_t)m * oc * 128 + (size_t)o * 128 + k] : 0.f;
    __nv_bfloat16 hi = __float2bfloat16(v);
    dhi[idx] = hi;
    dlo[idx] = __float2bfloat16(v - __bfloat162float(hi));
}

__global__ void prep_kv(__nv_bfloat16* __restrict__ dhi, __nv_bfloat16* __restrict__ dlo)
{
    int idx = blockIdx.x * blockDim.x + threadIdx.x;
    if (idx >= 16384) return;
    int o = idx >> 7, k = idx & 127;
    float v = g_kvs[k * 128 + o];
    __nv_bfloat16 hi = __float2bfloat16(v);
    dhi[(size_t)30 * 16384 + idx] = hi;
    dlo[(size_t)30 * 16384 + idx] = __float2bfloat16(v - __bfloat162float(hi));
}

// ------------------- tensor-core GEMM: up to 3 products sharing A -------------------
// Each CTA processes TWO 128-row blocks; block 1 runs products in REVERSE order so
// resident B tiles in the double buffers are reused (only nout==3 reloads one tile).
#define ACT_NONE 0
#define ACT_RELU 1
#define ACT_SIGM 2

#define AM_PLAIN 0
#define AM_LN    1
#define AM_ATTN  2

struct TCParams {
    const float* A; int nrows; int nout; int amode;
    const float* lng; const float* lnb;          // LN / ATTN params
    const float* q; const float* hg;             // ATTN: q rows, gate rows
    const __nv_bfloat16* bhi[3]; const __nv_bfloat16* blo[3];
    const float* bias[3]; float* out[3];
    int oc[3]; int ldc[3]; int act[3]; int sdinv[3]; int strm[3];
};

#define SA 136                       // smem row stride in bf16 elems (272B)
#define SM_TILE (128 * SA * 2)       // 34816 bytes per tile image
#define OFF_A_HI 0
#define OFF_A_LO SM_TILE
#define OFF_B(buf, img) ((uint32_t)(2 + (buf) * 2 + (img)) * SM_TILE)
#define SMEM_TOTAL (6 * SM_TILE)     // 208896 bytes

__global__ __launch_bounds__(512, 1) void gemm_tc(TCParams p, int gpair)
{
    extern __shared__ __align__(16) char smem[];
    uint32_t sb = smem_u32(smem);
    int t = threadIdx.x;
    int lane = t & 31, wid = t >> 5;
    int wm = wid >> 2, wn = wid & 3;       // warp grid 4x4 -> warp tile 32x32

    int g = lane >> 3, l7 = lane & 7;
    uint32_t a_row  = (uint32_t)(wm * 32 + (g & 1) * 8 + l7);
    uint32_t a_coff = (uint32_t)((g >> 1) * 8);
    uint32_t b_row  = (uint32_t)(wn * 32 + (g >> 1) * 8 + l7);
    uint32_t b_coff = (uint32_t)((g & 1) * 8);

    for (int blk = 0; blk < 2; blk++) {
        int row0 = (blockIdx.x + blk * gpair) * 128;
        if (row0 >= p.nrows) break;
        bool rev = (blk == 1);

        // ---- prefetch first B (block 0 only; block 1 reuses resident tile) ----
        if (!rev) {
            const char* sh = (const char*)p.bhi[0];
            const char* sl = (const char*)p.blo[0];
#pragma unroll
            for (int i = 0; i < 4; i++) {
                int idx = i * 512 + t;
                int r = idx >> 4, c8 = (idx & 15) * 8;
                uint32_t boff = (uint32_t)r * (SA * 2) + c8 * 2;
                cpa16(sb + OFF_B(0, 0) + boff, sh + (size_t)idx * 16);
                cpa16(sb + OFF_B(0, 1) + boff, sl + (size_t)idx * 16);
            }
            CPA_COMMIT();
        }

        // ---- A load (+ optional fused row transform) + split to bf16 hi/lo ----
#pragma unroll
        for (int i = 0; i < 8; i++) {
            int r = i * 16 + wid;
            int gr = row0 + r;
            int c0 = lane * 4;
            float4 v = make_float4(0.f, 0.f, 0.f, 0.f);
            if (gr < p.nrows) v = *(const float4*)(p.A + (size_t)gr * 128 + c0);

            if (p.amode == AM_LN) {
                float s1 = v.x + v.y + v.z + v.w;
                float s2 = v.x * v.x + v.y * v.y + v.z * v.z + v.w * v.w;
                s1 = wsumf(s1); s2 = wsumf(s2);
                float mu = s1 * (1.f / 128.f);
                float var = s2 * (1.f / 128.f) - mu * mu;
                float rs = rsqrtf(var + 1e-5f);
                v.x = (v.x - mu) * rs * p.lng[c0 + 0] + p.lnb[c0 + 0];
                v.y = (v.y - mu) * rs * p.lng[c0 + 1] + p.lnb[c0 + 1];
                v.z = (v.z - mu) * rs * p.lng[c0 + 2] + p.lnb[c0 + 2];
                v.w = (v.w - mu) * rs * p.lng[c0 + 3] + p.lnb[c0 + 3];
            } else if (p.amode == AM_ATTN) {
                float4 qv = make_float4(0, 0, 0, 0), hv = qv;
                if (gr < p.nrows) {
                    qv = *(const float4*)(p.q  + (size_t)gr * 128 + c0);
                    hv = *(const float4*)(p.hg + (size_t)gr * 128 + c0);
                }
                float4 ksv = *(const float4*)(g_kvs + 16384 + c0);
                float den = qv.x * ksv.x + qv.y * ksv.y + qv.z * ksv.z + qv.w * ksv.w;
                den = wsumf(den);
                float inv = 1.f / (den + 1e-6f);
                v.x *= inv; v.y *= inv; v.z *= inv; v.w *= inv;
                float s1 = v.x + v.y + v.z + v.w;
                float s2 = v.x * v.x + v.y * v.y + v.z * v.z + v.w * v.w;
                s1 = wsumf(s1); s2 = wsumf(s2);
                float mu = s1 * (1.f / 128.f);
                float var = s2 * (1.f / 128.f) - mu * mu;
                float rs = rsqrtf(var + 1e-5f);
                v.x = ((v.x - mu) * rs * p.lng[c0 + 0] + p.lnb[c0 + 0]) * (hv.x + 0.9f);
                v.y = ((v.y - mu) * rs * p.lng[c0 + 1] + p.lnb[c0 + 1]) * (hv.y + 0.9f);
                v.z = ((v.z - mu) * rs * p.lng[c0 + 2] + p.lnb[c0 + 2]) * (hv.z + 0.9f);
                v.w = ((v.w - mu) * rs * p.lng[c0 + 3] + p.lnb[c0 + 3]) * (hv.w + 0.9f);
            }

            uint32_t h0, h1, l0, l1;
            splitpack(v.x, v.y, h0, l0);
            splitpack(v.z, v.w, h1, l1);
            uint32_t boff = (uint32_t)r * (SA * 2) + (uint32_t)c0 * 2;
            *(uint2*)(smem + OFF_A_HI + boff) = make_uint2(h0, h1);
            *(uint2*)(smem + OFF_A_LO + boff) = make_uint2(l0, l1);
        }
        if (!rev) CPA_WAIT0();
        __syncthreads();

        for (int jj = 0; jj < p.nout; jj++) {
            int j = rev ? (p.nout - 1 - jj) : jj;
            int nextj = rev ? (j - 1) : (j + 1);
            bool have_next = rev ? (nextj >= 0) : (nextj < p.nout);
            // block 1: buffers hold B[nout-1] (buf (nout-1)&1) and, for nout>=2, B[nout-2];
            // only nout==3's j==0 tile needs a reload.
            bool next_resident = rev && !(p.nout == 3 && nextj == 0);

            if (have_next && !next_resident) {
                const char* sh = (const char*)p.bhi[nextj];
                const char* sl = (const char*)p.blo[nextj];
                uint32_t bufh = OFF_B(nextj & 1, 0), bufl = OFF_B(nextj & 1, 1);
#pragma unroll
                for (int i = 0; i < 4; i++) {
                    int idx = i * 512 + t;
                    int r = idx >> 4, c8 = (idx & 15) * 8;
                    uint32_t boff = (uint32_t)r * (SA * 2) + c8 * 2;
                    cpa16(sb + bufh + boff, sh + (size_t)idx * 16);
                    cpa16(sb + bufl + boff, sl + (size_t)idx * 16);
                }
                CPA_COMMIT();
            }

            float acc[2][4][4];
#pragma unroll
            for (int mt = 0; mt < 2; mt++)
#pragma unroll
                for (int nt = 0; nt < 4; nt++)
#pragma unroll
                    for (int q2 = 0; q2 < 4; q2++) acc[mt][nt][q2] = 0.f;

            uint32_t obh = OFF_B(j & 1, 0), obl = OFF_B(j & 1, 1);
#pragma unroll
            for (int ks = 0; ks < 8; ks++) {
                uint32_t ah[2][4], al[2][4];
#pragma unroll
                for (int mt = 0; mt < 2; mt++) {
                    uint32_t off = ((a_row + mt * 16) * SA + ks * 16 + a_coff) * 2;
                    ldmat4(ah[mt][0], ah[mt][1], ah[mt][2], ah[mt][3], sb + OFF_A_HI + off);
                    ldmat4(al[mt][0], al[mt][1], al[mt][2], al[mt][3], sb + OFF_A_LO + off);
                }
                uint32_t bh[4][2], bl[4][2];
#pragma unroll
                for (int np = 0; np < 2; np++) {
                    uint32_t off = ((b_row + np * 16) * SA + ks * 16 + b_coff) * 2;
                    ldmat4(bh[2 * np][0], bh[2 * np][1], bh[2 * np + 1][0], bh[2 * np + 1][1],
                           sb + obh + off);
                    ldmat4(bl[2 * np][0], bl[2 * np][1], bl[2 * np + 1][0], bl[2 * np + 1][1],
                           sb + obl + off);
                }
#pragma unroll
                for (int mt = 0; mt < 2; mt++)
#pragma unroll
                    for (int nt = 0; nt < 4; nt++) {
                        mma16816(acc[mt][nt], ah[mt], bh[nt]);
                        mma16816(acc[mt][nt], ah[mt], bl[nt]);
                        mma16816(acc[mt][nt], al[mt], bh[nt]);
                    }
            }

            // ---- epilogue (register-only) ----
            {
                const float* bs = p.bias[j];
                float* outp = p.out[j];
                int oc = p.oc[j], ldc = p.ldc[j], act = p.act[j];
                int sdv = p.sdinv[j], strm = p.strm[j];
#pragma unroll
                for (int mt = 0; mt < 2; mt++) {
                    int r0 = row0 + wm * 32 + mt * 16 + (lane >> 2);
                    int r1 = r0 + 8;
                    float sc0 = 1.f, sc1 = 1.f;
                    if (sdv) {
                        if (r0 < p.nrows) sc0 = g_dinv[r0];
                        if (r1 < p.nrows) sc1 = g_dinv[r1];
                    }
#pragma unroll
                    for (int nt = 0; nt < 4; nt++) {
                        int c = wn * 32 + nt * 8 + (lane & 3) * 2;
                        if (c >= oc) continue;
                        float b0 = bs ? bs[c] : 0.f;
                        float b1 = bs ? bs[c + 1] : 0.f;
                        float d0 = acc[mt][nt][0] + b0;
                        float d1 = acc[mt][nt][1] + b1;
                        float d2 = acc[mt][nt][2] + b0;
                        float d3 = acc[mt][nt][3] + b1;
                        if (act == ACT_RELU) {
                            d0 = fmaxf(d0, 0.f); d1 = fmaxf(d1, 0.f);
                            d2 = fmaxf(d2, 0.f); d3 = fmaxf(d3, 0.f);
                        } else if (act == ACT_SIGM) {
                            d0 = 1.f / (1.f + expf(-d0));
                            d1 = 1.f / (1.f + expf(-d1));
                            d2 = 1.f / (1.f + expf(-d2));
                            d3 = 1.f / (1.f + expf(-d3));
                        }
                        d0 *= sc0; d1 *= sc0; d2 *= sc1; d3 *= sc1;
                        if (strm) {
                            if (r0 < p.nrows) stcs2(outp + (size_t)r0 * ldc + c, d0, d1);
                            if (r1 < p.nrows) stcs2(outp + (size_t)r1 * ldc + c, d2, d3);
                        } else {
                            if (r0 < p.nrows) *(float2*)(outp + (size_t)r0 * ldc + c) = make_float2(d0, d1);
                            if (r1 < p.nrows) *(float2*)(outp + (size_t)r1 * ldc + c) = make_float2(d2, d3);
                        }
                    }
                }
            }

            if (have_next) {
                if (!next_resident) CPA_WAIT0();
                __syncthreads();
            }
        }
        __syncthreads();   // protect A/B images before next block overwrites
    }
}

// ------------------- edge dtype detect + CSR build -------------------
__global__ void detect_k(const int* __restrict__ w, int nwords)
{
    __shared__ int any;
    if (threadIdx.x == 0) any = 0;
    __syncthreads();
    int npairs = min(nwords >> 1, 2048);
    for (int i = threadIdx.x; i < npairs; i += blockDim.x)
        if (w[2 * i + 1] != 0) atomicOr(&any, 1);
    __syncthreads();
    if (threadIdx.x == 0) g_is64 = (any == 0) ? 1 : 0;
}

__device__ __forceinline__ int edge_at(const void* ei, long long idx)
{
    return g_is64 ? (int)((const long long*)ei)[idx] : ((const int*)ei)[idx];
}

__global__ void hist_k(const void* __restrict__ ei, long long eoff, int ne)
{
    for (int e = blockIdx.x * blockDim.x + threadIdx.x; e < ne; e += gridDim.x * blockDim.x)
        atomicAdd(&g_deg[edge_at(ei, eoff + e)], 1);
}

__global__ void scan1(int n)
{
    __shared__ int wsum[32];
    int t = threadIdx.x;
    int idx = blockIdx.x * 4096 + t * 4;
    int v0 = (idx + 0 < n) ? g_deg[idx + 0] : 0;
    int v1 = (idx + 1 < n) ? g_deg[idx + 1] : 0;
    int v2 = (idx + 2 < n) ? g_deg[idx + 2] : 0;
    int v3 = (idx + 3 < n) ? g_deg[idx + 3] : 0;
    if (idx + 0 < n) g_dinv[idx + 0] = rsqrtf((float)(v0 + 1));
    if (idx + 1 < n) g_dinv[idx + 1] = rsqrtf((float)(v1 + 1));
    if (idx + 2 < n) g_dinv[idx + 2] = rsqrtf((float)(v2 + 1));
    if (idx + 3 < n) g_dinv[idx + 3] = rsqrtf((float)(v3 + 1));
    int tsum = v0 + v1 + v2 + v3;
    int lane = t & 31, w = t >> 5;
    int inc = tsum;
#pragma unroll
    for (int o = 1; o < 32; o <<= 1) {
        int y = __shfl_up_sync(0xffffffffu, inc, o);
        if (lane >= o) inc += y;
    }
    if (lane == 31) wsum[w] = inc;
    __syncthreads();
    if (w == 0) {
        int y = wsum[lane];
#pragma unroll
        for (int o = 1; o < 32; o <<= 1) {
            int z = __shfl_up_sync(0xffffffffu, y, o);
            if (lane >= o) y += z;
        }
        wsum[lane] = y;
    }
    __syncthreads();
    int excl = inc - tsum + (w > 0 ? wsum[w - 1] : 0);
    if (idx + 0 < n) g_rowp[idx + 0] = excl;
    if (idx + 1 < n) g_rowp[idx + 1] = excl + v0;
    if (idx + 2 < n) g_rowp[idx + 2] = excl + v0 + v1;
    if (idx + 3 < n) g_rowp[idx + 3] = excl + v0 + v1 + v2;
    if (t == 0) g_bsum[blockIdx.x] = wsum[31];
}

__global__ void scan2(int nb)
{
    if (threadIdx.x == 0 && blockIdx.x == 0) {
        int s = 0;
        for (int i = 0; i < nb; i++) { int t = g_bsum[i]; g_bsum[i] = s; s += t; }
    }
}

__global__ void scan3(int n, int total)
{
    int t = threadIdx.x;
    int idx = blockIdx.x * 4096 + t * 4;
    int off = g_bsum[blockIdx.x];
#pragma unroll
    for (int j = 0; j < 4; j++)
        if (idx + j < n) g_rowp[idx + j] += off;
    if (blockIdx.x == 0 && t == 0) g_rowp[n] = total;
}

__global__ void scatter_k(const void* __restrict__ ei, long long eoff, int ne)
{
    for (int e = blockIdx.x * blockDim.x + threadIdx.x; e < ne; e += gridDim.x * blockDim.x) {
        int d = edge_at(ei, eoff + e);
        int s = edge_at(ei, e);
        int pos = g_rowp[d] + atomicAdd(&g_fill[d], 1);
        g_col[pos] = s;
    }
}

// ------------------- kv = k^T v via HMMA (3-term split-bf16) + fused ksum -------
__global__ __launch_bounds__(512) void kv_tc(const float* __restrict__ kk,
                                             const float* __restrict__ vv, int n)
{
    __shared__ __align__(16) __nv_bfloat16 skh[16][SA], skl[16][SA];
    __shared__ __align__(16) __nv_bfloat16 svh[16][SA], svl[16][SA];
    __shared__ float kss[128];
    int t = threadIdx.x, lane = t & 31, wid = t >> 5;
    int wm = wid >> 2, wn = wid & 3;
    int base = blockIdx.x * 512;
    int rows = min(512, n - base);
    int nch = (rows + 15) >> 4;

    if (t < 128) kss[t] = 0.f;

    int lr = wid;
    int c4 = lane * 4;

    uint32_t kh_b = smem_u32(&skh[0][0]);
    uint32_t kl_b = smem_u32(&skl[0][0]);
    uint32_t vh_b = smem_u32(&svh[0][0]);
    uint32_t vl_b = smem_u32(&svl[0][0]);

    int g = lane >> 3, l7 = lane & 7;
    uint32_t a_off = (uint32_t)((g >> 1) * 8 + l7) * (SA * 2) + (uint32_t)(wm * 32 + (g & 1) * 8) * 2;
    uint32_t b_off = (uint32_t)((g & 1) * 8 + l7) * (SA * 2) + (uint32_t)(wn * 32 + (g >> 1) * 8) * 2;

    float acc[2][4][4];
#pragma unroll
    for (int mt = 0; mt < 2; mt++)
#pragma unroll
        for (int nt = 0; nt < 4; nt++)
#pragma unroll
            for (int q = 0; q < 4; q++) acc[mt][nt][q] = 0.f;

    float4 ksacc = make_float4(0.f, 0.f, 0.f, 0.f);

    float4 kreg = make_float4(0, 0, 0, 0), vreg = kreg;
    {
        int gr = base + lr;
        if (gr < n) {
            kreg = *(const float4*)(kk + (size_t)gr * 128 + c4);
            vreg = *(const float4*)(vv + (size_t)gr * 128 + c4);
        }
    }

    for (int c = 0; c < nch; c++) {
        __syncthreads();
        uint32_t h0, h1, l0, l1;
        splitpack(kreg.x, kreg.y, h0, l0);
        splitpack(kreg.z, kreg.w, h1, l1);
        *(uint2*)&skh[lr][c4] = make_uint2(h0, h1);
        *(uint2*)&skl[lr][c4] = make_uint2(l0, l1);
        ksacc.x += kreg.x; ksacc.y += kreg.y; ksacc.z += kreg.z; ksacc.w += kreg.w;
        splitpack(vreg.x, vreg.y, h0, l0);
        splitpack(vreg.z, vreg.w, h1, l1);
        *(uint2*)&svh[lr][c4] = make_uint2(h0, h1);
        *(uint2*)&svl[lr][c4] = make_uint2(l0, l1);
        if (c + 1 < nch) {
            int gr = base + (c + 1) * 16 + lr;
            kreg = vreg = make_float4(0, 0, 0, 0);
            if (gr < n) {
                kreg = *(const float4*)(kk + (size_t)gr * 128 + c4);
                vreg = *(const float4*)(vv + (size_t)gr * 128 + c4);
            }
        }
        __syncthreads();
        uint32_t ah[2][4], al[2][4];
#pragma unroll
        for (int mt = 0; mt < 2; mt++) {
            ldmat4t(ah[mt][0], ah[mt][1], ah[mt][2], ah[mt][3], kh_b + a_off + mt * 32);
            ldmat4t(al[mt][0], al[mt][1], al[mt][2], al[mt][3], kl_b + a_off + mt * 32);
        }
        uint32_t bh[4][2], bl[4][2];
#pragma unroll
        for (int np = 0; np < 2; np++) {
            ldmat4t(bh[2 * np][0], bh[2 * np][1], bh[2 * np + 1][0], bh[2 * np + 1][1],
                    vh_b + b_off + np * 32);
            ldmat4t(bl[2 * np][0], bl[2 * np][1], bl[2 * np + 1][0], bl[2 * np + 1][1],
                    vl_b + b_off + np * 32);
        }
#pragma unroll
        for (int mt = 0; mt < 2; mt++)
#pragma unroll
            for (int nt = 0; nt < 4; nt++) {
                mma16816(acc[mt][nt], ah[mt], bh[nt]);
                mma16816(acc[mt][nt], ah[mt], bl[nt]);
                mma16816(acc[mt][nt], al[mt], bh[nt]);
            }
    }

#pragma unroll
    for (int mt = 0; mt < 2; mt++) {
        int r0 = wm * 32 + mt * 16 + (lane >> 2);
        int r1 = r0 + 8;
#pragma unroll
        for (int nt = 0; nt < 4; nt++) {
            int cc = wn * 32 + nt * 8 + (lane & 3) * 2;
            atomicAdd(&g_kvs[r0 * 128 + cc],     acc[mt][nt][0]);
            atomicAdd(&g_kvs[r0 * 128 + cc + 1], acc[mt][nt][1]);
            atomicAdd(&g_kvs[r1 * 128 + cc],     acc[mt][nt][2]);
            atomicAdd(&g_kvs[r1 * 128 + cc + 1], acc[mt][nt][3]);
        }
    }
    atomicAdd(&kss[c4 + 0], ksacc.x);
    atomicAdd(&kss[c4 + 1], ksacc.y);
    atomicAdd(&kss[c4 + 2], ksacc.z);
    atomicAdd(&kss[c4 + 3], ksacc.w);
    __syncthreads();
    if (t < 128) atomicAdd(&g_kvs[16384 + t], kss[t]);
}

// ------------------- fused SpMM + GCN-layer epilogue (warp per node) ------------
__global__ __launch_bounds__(256)
void spmm_epi(const float* __restrict__ bg,
              const float* __restrict__ bng, const float* __restrict__ bnb,
              const float* __restrict__ bnrm, const float* __restrict__ bnrv,
              const float* __restrict__ lng, const float* __restrict__ lnb,
              int n, int first, int last)
{
    int w = (blockIdx.x * blockDim.x + threadIdx.x) >> 5;
    int lane = threadIdx.x & 31;
    if (w >= n) return;
    int c0 = lane * 4;

    float4 acc = *(const float4*)(g_xw + (size_t)w * 128 + c0);   // self term y_w
    int e0 = g_rowp[w], e1 = g_rowp[w + 1];
    int c_next = (e0 < e1) ? g_col[e0] : 0;
    for (int e = e0; e < e1; e++) {
        int c = c_next;
        if (e + 1 < e1) c_next = g_col[e + 1];
        float4 v = *(const float4*)(g_xw + (size_t)c * 128 + c0);
        acc.x += v.x; acc.y += v.y; acc.z += v.z; acc.w += v.w;
    }
    float di = g_dinv[w];
    float4 lv = ldcs4(g_lin + (size_t)w * 128 + c0);
    float4 xv;
    xv.x = acc.x * di + bg[c0 + 0] + lv.x;
    xv.y = acc.y * di + bg[c0 + 1] + lv.y;
    xv.z = acc.z * di + bg[c0 + 2] + lv.z;
    xv.w = acc.w * di + bg[c0 + 3] + lv.w;
#pragma unroll
    for (int j = 0; j < 4; j++) {
        float s = bng[c0 + j] * rsqrtf(bnrv[c0 + j] + 1e-5f);
        float* p = &xv.x + j;
        *p = fmaxf((*p - bnrm[c0 + j]) * s + bnb[c0 + j], 0.f);
    }
    float4 hv = ldcs4(g_h + (size_t)w * 128 + c0);
    float4 tv;
    tv.x = hv.x * xv.x; tv.y = hv.y * xv.y; tv.z = hv.z * xv.z; tv.w = hv.w * xv.w;
    float s1 = tv.x + tv.y + tv.z + tv.w;
    float s2 = tv.x * tv.x + tv.y * tv.y + tv.z * tv.z + tv.w * tv.w;
    s1 = wsumf(s1); s2 = wsumf(s2);
    float mu = s1 * (1.f / 128.f);
    float var = s2 * (1.f / 128.f) - mu * mu;
    float rs = rsqrtf(var + 1e-5f);
#pragma unroll
    for (int j = 0; j < 4; j++) {
        float* pt = &tv.x + j;
        float* px = &xv.x + j;
        float y = (*pt - mu) * rs * lng[c0 + j] + lnb[c0 + j];
        *px = 0.1f * y + 0.9f * (*px);
    }
    float4 xl = make_float4(0, 0, 0, 0);
    if (!first) xl = ldcs4(g_xloc + (size_t)w * 128 + c0);
    xl.x += xv.x; xl.y += xv.y; xl.z += xv.z; xl.w += xv.w;
    stcs4(g_xloc + (size_t)w * 128 + c0, xl);
    if (!last) stcs4(g_x + (size_t)w * 128 + c0, xv);
}

// ------------------- host orchestration -------------------
static inline void fill1(TCParams& p, int i, const __nv_bfloat16* bh, const __nv_bfloat16* bl,
                         const float* bias, float* out, int oc, int ldc, int act,
                         int sdv = 0, int strm = 0)
{
    p.bhi[i] = bh; p.blo[i] = bl; p.bias[i] = bias; p.out[i] = out;
    p.oc[i] = oc; p.ldc[i] = ldc; p.act[i] = act; p.sdinv[i] = sdv; p.strm[i] = strm;
}

extern "C" void kernel_launch(void* const* d_in, const int* in_sizes, int n_in,
                              void* d_out, int out_size)
{
    const float* in_x  = (const float*)d_in[0];
    const void*  ei    = d_in[1];
    const float* Wh    = (const float*)d_in[2];
    const float* bh    = (const float*)d_in[3];
    const float* Wg    = (const float*)d_in[4];
    const float* bg    = (const float*)d_in[5];
    const float* Wl    = (const float*)d_in[6];
    const float* bl    = (const float*)d_in[7];
    const float* ln_g  = (const float*)d_in[8];
    const float* ln_b  = (const float*)d_in[9];
    const float* bn_g  = (const float*)d_in[10];
    const float* bn_b  = (const float*)d_in[11];
    const float* bn_rm = (const float*)d_in[12];
    const float* bn_rv = (const float*)d_in[13];
    const float* gWh   = (const float*)d_in[14];
    const float* gbh   = (const float*)d_in[15];
    const float* gWk   = (const float*)d_in[16];
    const float* gWv   = (const float*)d_in[17];
    const float* gln_g = (const float*)d_in[18];
    const float* gln_b = (const float*)d_in[19];
    const float* gWo   = (const float*)d_in[20];
    const float* gbo   = (const float*)d_in[21];
    const float* f_ln_g = (const float*)d_in[22];
    const float* f_ln_b = (const float*)d_in[23];
    const float* Wp    = (const float*)d_in[24];
    const float* bp    = (const float*)d_in[25];

    int n  = in_sizes[0] / 128;
    int ne = in_sizes[1] / 2;

    float *px, *ph, *pxw, *plin, *pxloc, *pxg, *pk, *pkvs;
    __nv_bfloat16 *pBhi, *pBlo;
    int *pdeg, *pfill;
    cudaGetSymbolAddress((void**)&px, g_x);
    cudaGetSymbolAddress((void**)&ph, g_h);
    cudaGetSymbolAddress((void**)&pxw, g_xw);
    cudaGetSymbolAddress((void**)&plin, g_lin);
    cudaGetSymbolAddress((void**)&pxloc, g_xloc);
    cudaGetSymbolAddress((void**)&pxg, g_xg);
    cudaGetSymbolAddress((void**)&pk, g_k);
    cudaGetSymbolAddress((void**)&pkvs, g_kvs);
    cudaGetSymbolAddress((void**)&pdeg, g_deg);
    cudaGetSymbolAddress((void**)&pfill, g_fill);
    cudaGetSymbolAddress((void**)&pBhi, g_Bhi);
    cudaGetSymbolAddress((void**)&pBlo, g_Blo);

    cudaFuncSetAttribute(gemm_tc, cudaFuncAttributeMaxDynamicSharedMemorySize, SMEM_TOTAL);

    int gg = (n + 127) / 128;
    int gpair = (gg + 1) / 2;
    int wg = (n * 32 + 255) / 256;
    int nblk = (n + 4095) / 4096;

    prep_all<<<(30 * 16384 + 255) / 256, 256>>>(Wh, Wg, Wl, gWh, gWk, gWv, gWo, Wp, pBhi, pBlo);
    detect_k<<<1, 256>>>((const int*)ei, ne * 2);
    cudaMemsetAsync(pdeg, 0, (size_t)n * 4);
    hist_k<<<2048, 256>>>(ei, (long long)ne, ne);
    scan1<<<nblk, 1024>>>(n);

    // first GEMM (layer 1) — A = in_x
    {
        TCParams p = {};
        p.A = in_x; p.nrows = n; p.nout = 3; p.amode = AM_PLAIN;
        fill1(p, 0, pBhi + (size_t)0 * 16384,  pBlo + (size_t)0 * 16384,  bh, ph,   128, 128, ACT_RELU, 0, 1);
        fill1(p, 1, pBhi + (size_t)7 * 16384,  pBlo + (size_t)7 * 16384,  nullptr, pxw,  128, 128, ACT_NONE, 1, 0);
        fill1(p, 2, pBhi + (size_t)14 * 16384, pBlo + (size_t)14 * 16384, bl, plin, 128, 128, ACT_NONE, 0, 1);
        gemm_tc<<<gpair, 512, SMEM_TOTAL>>>(p, gpair);
    }

    scan2<<<1, 32>>>(nblk);
    scan3<<<nblk, 1024>>>(n, ne);
    cudaMemsetAsync(pfill, 0, (size_t)n * 4);
    scatter_k<<<2048, 256>>>(ei, (long long)ne, ne);

    spmm_epi<<<wg, 256>>>(bg, bn_g, bn_b, bn_rm, bn_rv, ln_g, ln_b, n, 1, 0);

    for (int i = 1; i < 7; i++) {
        TCParams p = {};
        p.A = px; p.nrows = n; p.nout = 3; p.amode = AM_PLAIN;
        fill1(p, 0, pBhi + (size_t)i * 16384,        pBlo + (size_t)i * 16384,        bh + i * 128, ph,   128, 128, ACT_RELU, 0, 1);
        fill1(p, 1, pBhi + (size_t)(7 + i) * 16384,  pBlo + (size_t)(7 + i) * 16384,  nullptr,      pxw,  128, 128, ACT_NONE, 1, 0);
        fill1(p, 2, pBhi + (size_t)(14 + i) * 16384, pBlo + (size_t)(14 + i) * 16384, bl + i * 128, plin, 128, 128, ACT_NONE, 0, 1);
        gemm_tc<<<gpair, 512, SMEM_TOTAL>>>(p, gpair);
        spmm_epi<<<wg, 256>>>(bg + i * 128, bn_g + i * 128, bn_b + i * 128,
                              bn_rm + i * 128, bn_rv + i * 128,
                              ln_g + i * 128, ln_b + i * 128, n, 0, i == 6);
    }

    // global attention (LN fused into entry GEMM; attn_epi fused into out-GEMM)
    for (int j = 0; j < 2; j++) {
        {
            TCParams p = {};
            p.nrows = n; p.nout = 3;
            if (j == 0) { p.A = pxloc; p.amode = AM_LN; p.lng = f_ln_g; p.lnb = f_ln_b; }
            else        { p.A = pxg;   p.amode = AM_PLAIN; }
            fill1(p, 0, pBhi + (size_t)(21 + j) * 16384, pBlo + (size_t)(21 + j) * 16384, gbh + j * 128, ph,  128, 128, ACT_NONE, 0, 1);
            fill1(p, 1, pBhi + (size_t)(23 + j) * 16384, pBlo + (size_t)(23 + j) * 16384, nullptr,       pk,  128, 128, ACT_SIGM, 0, 0);
            fill1(p, 2, pBhi + (size_t)(25 + j) * 16384, pBlo + (size_t)(25 + j) * 16384, nullptr,       pxw, 128, 128, ACT_NONE, 0, 0);
            gemm_tc<<<gpair, 512, SMEM_TOTAL>>>(p, gpair);
        }
        cudaMemsetAsync(pkvs, 0, (128 * 128 + 128) * 4);
        kv_tc<<<(n + 511) / 512, 512>>>(pk, pxw, n);
        prep_kv<<<(16384 + 255) / 256, 256>>>(pBhi, pBlo);
        {
            TCParams p = {};
            p.A = pk; p.nrows = n; p.nout = 1; p.amode = AM_PLAIN;
            fill1(p, 0, pBhi + (size_t)30 * 16384, pBlo + (size_t)30 * 16384, nullptr, plin, 128, 128, ACT_NONE);
            gemm_tc<<<gpair, 512, SMEM_TOTAL>>>(p, gpair);
        }
        {
            TCParams p = {};
            p.A = plin; p.nrows = n; p.nout = 1; p.amode = AM_ATTN;
            p.lng = gln_g + j * 128; p.lnb = gln_b + j * 128;
            p.q = pk; p.hg = ph;
            fill1(p, 0, pBhi + (size_t)(27 + j) * 16384, pBlo + (size_t)(27 + j) * 16384, gbo + j * 128, pxg, 128, 128, ACT_RELU);
            gemm_tc<<<gpair, 512, SMEM_TOTAL>>>(p, gpair);
        }
    }

    // final projection (oc=40)
    {
        TCParams p = {};
        p.A = pxg; p.nrows = n; p.nout = 1; p.amode = AM_PLAIN;
        fill1(p, 0, pBhi + (size_t)29 * 16384, pBlo + (size_t)29 * 16384, bp, (float*)d_out, 40, 40, ACT_NONE);
        gemm_tc<<<gpair, 512, SMEM_TOTAL>>>(p, gpair);
    }
}